// round 12
// baseline (speedup 1.0000x reference)
#include <cuda_runtime.h>
#include <cuda_bf16.h>
#include <cstdint>
#include <cstddef>

// ---------------------------------------------------------------------------
// Problem constants
// ---------------------------------------------------------------------------
#define N_BATCH 64
#define M0 4096
#define M1 1024
#define K_CHEB 25
#define F0 32
#define F1 64
#define NC1 64
#define NC2 2048
#define SL1 (M0*NC1)
#define SL2 (M1*NC2)
#define Z1 8
#define KZ1 (M0/Z1)     // 512

// ---------------------------------------------------------------------------
// Device scratch
// ---------------------------------------------------------------------------
__device__ float g_T1[K_CHEB * SL1];
__device__ float g_T2[(size_t)K_CHEB * SL2];
__device__ float g_PZ[(size_t)Z1 * SL1];
__device__ float g_OUT2[N_BATCH * 16384];
__device__ float g_P[8 * N_BATCH * 512];
__device__ float g_Yh[N_BATCH * 512];
__device__ __nv_bfloat16 g_L0h[(size_t)M0 * M0];
__device__ __nv_bfloat16 g_L0l[(size_t)M0 * M0];
__device__ __nv_bfloat16 g_L1h[(size_t)M1 * M1];
__device__ __nv_bfloat16 g_L1l[(size_t)M1 * M1];
// pre-split, pre-transposed state buffers: [j][v] (N-major)
__device__ __nv_bfloat16 g_Bh1[(size_t)NC1 * M0];
__device__ __nv_bfloat16 g_Bl1[(size_t)NC1 * M0];
__device__ __nv_bfloat16 g_Bh2[2][(size_t)NC2 * M1];   // ping-pong
__device__ __nv_bfloat16 g_Bl2[2][(size_t)NC2 * M1];

// ---------------------------------------------------------------------------
// MMA / async-copy helpers (portable Ampere-era ops)
// ---------------------------------------------------------------------------
__device__ __forceinline__ uint32_t smem_u32(const void* p) {
    uint32_t a;
    asm("{ .reg .u64 t; cvta.to.shared.u64 t, %1; cvt.u32.u64 %0, t; }"
        : "=r"(a) : "l"(p));
    return a;
}
__device__ __forceinline__ void ldsm_x4(uint32_t* r, uint32_t addr) {
    asm volatile("ldmatrix.sync.aligned.m8n8.x4.shared.b16 {%0,%1,%2,%3}, [%4];"
        : "=r"(r[0]), "=r"(r[1]), "=r"(r[2]), "=r"(r[3]) : "r"(addr));
}
__device__ __forceinline__ void ldsm_x2(uint32_t* r, uint32_t addr) {
    asm volatile("ldmatrix.sync.aligned.m8n8.x2.shared.b16 {%0,%1}, [%2];"
        : "=r"(r[0]), "=r"(r[1]) : "r"(addr));
}
__device__ __forceinline__ void mma16816(float* c, const uint32_t* a,
                                         const uint32_t* b) {
    asm volatile(
        "mma.sync.aligned.m16n8k16.row.col.f32.bf16.bf16.f32 "
        "{%0,%1,%2,%3}, {%4,%5,%6,%7}, {%8,%9}, {%0,%1,%2,%3};"
        : "+f"(c[0]), "+f"(c[1]), "+f"(c[2]), "+f"(c[3])
        : "r"(a[0]), "r"(a[1]), "r"(a[2]), "r"(a[3]), "r"(b[0]), "r"(b[1]));
}
__device__ __forceinline__ void cp16(uint32_t saddr, const void* g) {
    asm volatile("cp.async.cg.shared.global [%0], [%1], 16;"
        :: "r"(saddr), "l"(g) : "memory");
}
#define CP_COMMIT() asm volatile("cp.async.commit_group;" ::: "memory")
#define CP_WAIT1()  asm volatile("cp.async.wait_group 1;" ::: "memory")
#define CP_WAIT0()  asm volatile("cp.async.wait_group 0;" ::: "memory")

__device__ __forceinline__ void split2(float a, float b, uint32_t& h2, uint32_t& l2)
{
    __nv_bfloat16 ha = __float2bfloat16(a), hb = __float2bfloat16(b);
    float ra = __bfloat162float(ha), rb = __bfloat162float(hb);
    __nv_bfloat16 la = __float2bfloat16(a - ra), lb = __float2bfloat16(b - rb);
    h2 = (uint32_t)__bfloat16_as_ushort(ha) | ((uint32_t)__bfloat16_as_ushort(hb) << 16);
    l2 = (uint32_t)__bfloat16_as_ushort(la) | ((uint32_t)__bfloat16_as_ushort(lb) << 16);
}

// ---------------------------------------------------------------------------
// Prep: split fp32 matrix -> bf16 hi/lo (same layout)
// ---------------------------------------------------------------------------
__global__ void split_bf16(const float* __restrict__ src,
                           __nv_bfloat16* __restrict__ hi,
                           __nv_bfloat16* __restrict__ lo, int n4)
{
    int i = blockIdx.x * blockDim.x + threadIdx.x;
    if (i >= n4) return;
    float4 v = ((const float4*)src)[i];
    uint32_t h0, l0, h1, l1;
    split2(v.x, v.y, h0, l0);
    split2(v.z, v.w, h1, l1);
    ((uint2*)hi)[i] = make_uint2(h0, h1);
    ((uint2*)lo)[i] = make_uint2(l0, l1);
}

// ---------------------------------------------------------------------------
// split_trans: fp32 state X[M rows][NC cols] -> bf16 hi/lo transposed [NC][M]
// (used once: layer2 state 0)
// ---------------------------------------------------------------------------
__global__ __launch_bounds__(256)
void split_trans(const float* __restrict__ X,
                 __nv_bfloat16* __restrict__ Hi,
                 __nv_bfloat16* __restrict__ Lo, int M, int NC)
{
    __shared__ float s[64][33];
    int m0 = blockIdx.x * 64, nc0 = blockIdx.y * 32;
    int tx = threadIdx.x, ty = threadIdx.y;
    for (int r = ty; r < 64; r += 8)
        s[r][tx] = X[(size_t)(m0 + r) * NC + nc0 + tx];
    __syncthreads();
    for (int r = ty; r < 32; r += 8) {
        int j = nc0 + r;
        float a = s[tx * 2][r], b = s[tx * 2 + 1][r];
        uint32_t h2, l2;
        split2(a, b, h2, l2);
        ((uint32_t*)(Hi + (size_t)j * M + m0))[tx] = h2;
        ((uint32_t*)(Lo + (size_t)j * M + m0))[tx] = l2;
    }
}

// ---------------------------------------------------------------------------
// combine_split (layer1): C = s2*sum_z PZ - hasA*A  (fp32 [u][n]),
// plus transposed bf16 hi/lo [n][u] for the next GEMM's B.
// Tile 64 u x 32 n, block (32,8), grid (M0/64, NC1/32).
// ---------------------------------------------------------------------------
__global__ __launch_bounds__(256)
void combine_split(const float* __restrict__ Ap, float* __restrict__ Cp,
                   __nv_bfloat16* __restrict__ Hi, __nv_bfloat16* __restrict__ Lo,
                   float s2, int hasA)
{
    __shared__ float s[64][33];
    int m0 = blockIdx.x * 64, nc0 = blockIdx.y * 32;
    int tx = threadIdx.x, ty = threadIdx.y;
    for (int r = ty; r < 64; r += 8) {
        size_t off = (size_t)(m0 + r) * NC1 + nc0 + tx;
        float acc = 0.f;
#pragma unroll
        for (int z = 0; z < Z1; z++)
            acc += g_PZ[(size_t)z * SL1 + off];
        float c = s2 * acc;
        if (hasA) c -= Ap[off];
        Cp[off] = c;
        s[r][tx] = c;
    }
    __syncthreads();
    for (int r = ty; r < 32; r += 8) {
        int j = nc0 + r;
        uint32_t h2, l2;
        split2(s[tx * 2][r], s[tx * 2 + 1][r], h2, l2);
        ((uint32_t*)(Hi + (size_t)j * M0 + m0))[tx] = h2;
        ((uint32_t*)(Lo + (size_t)j * M0 + m0))[tx] = l2;
    }
}

// ---------------------------------------------------------------------------
// Transpose x (N,4096) -> T1 slab 0 as [u][n]
// ---------------------------------------------------------------------------
__global__ void transpose_x(const float* __restrict__ x, float* __restrict__ T0)
{
    __shared__ float s[32][33];
    int u0 = blockIdx.x * 32, n0 = blockIdx.y * 32;
    int tx = threadIdx.x, ty = threadIdx.y;
    for (int r = ty; r < 32; r += 8)
        s[r][tx] = x[(size_t)(n0 + r) * M0 + u0 + tx];
    __syncthreads();
    for (int r = ty; r < 32; r += 8)
        T0[(size_t)(u0 + r) * NC1 + n0 + tx] = s[tx][r];
}

// ---------------------------------------------------------------------------
// Tensor-core (mma.sync) Chebyshev GEMM, 128x64 CTA tile, 256 threads,
// cp.async 3-stage pipeline.
//   PARTIAL=1: raw D -> Cp slab blockIdx.z (layer1 split-K).
//   PARTIAL=0: C = s2*D - hasA*A; if doSplit, ALSO emit transposed bf16
//              hi/lo of C into Ho/Lo (next step's B), staged via smem.
// ---------------------------------------------------------------------------
#define ROWB   80
#define OFF_AH 0
#define OFF_AL 10240
#define OFF_BH 20480
#define OFF_BL 25600
#define STAGE_B 30720
#define NSTAGE 3
#define CSTR 68            // fp32 stride for C staging (128 x 68)

template<int PARTIAL>
__global__ __launch_bounds__(256)
void cheb_gemm_mma(const __nv_bfloat16* __restrict__ Lh,
                   const __nv_bfloat16* __restrict__ Ll,
                   const __nv_bfloat16* __restrict__ Bh,
                   const __nv_bfloat16* __restrict__ Bl,
                   const float* __restrict__ Ap,
                   float* __restrict__ Cp,
                   __nv_bfloat16* __restrict__ Ho,
                   __nv_bfloat16* __restrict__ Lo,
                   int M, int NC, int KLEN, float s2, int hasA, int doSplit)
{
    extern __shared__ __align__(16) char dsm[];
    const uint32_t sb = smem_u32(dsm);

    const int tid  = threadIdx.x;
    const int lane = tid & 31;
    const int wid  = tid >> 5;
    const int wm   = wid & 1;
    const int wn   = wid >> 1;
    const int u0   = blockIdx.y * 128;
    const int j0   = blockIdx.x * 64;
    const int kz   = blockIdx.z * KLEN;
    const int KT   = KLEN >> 5;

    const int ar0  = tid >> 2;
    const int ar1  = ar0 + 64;
    const int ac16 = (tid & 3) * 16;
    const int acol = (tid & 3) * 8;

    const __nv_bfloat16* gAh0 = Lh + (size_t)(u0 + ar0) * M + kz + acol;
    const __nv_bfloat16* gAh1 = Lh + (size_t)(u0 + ar1) * M + kz + acol;
    const __nv_bfloat16* gAl0 = Ll + (size_t)(u0 + ar0) * M + kz + acol;
    const __nv_bfloat16* gAl1 = Ll + (size_t)(u0 + ar1) * M + kz + acol;
    const __nv_bfloat16* gBh0 = Bh + (size_t)(j0 + ar0) * M + kz + acol;
    const __nv_bfloat16* gBl0 = Bl + (size_t)(j0 + ar0) * M + kz + acol;

    const uint32_t dA0 = ar0 * ROWB + ac16;
    const uint32_t dA1 = ar1 * ROWB + ac16;

    const uint32_t arow = (uint32_t)((wm * 64 + (lane & 15)) * ROWB
                                     + (lane >> 4) * 16);
    const uint32_t brow = (uint32_t)((wn * 16 + (lane & 7)) * ROWB
                                     + ((lane >> 3) & 1) * 16);

    float acc[4][2][4];
#pragma unroll
    for (int ma = 0; ma < 4; ma++)
#pragma unroll
        for (int na = 0; na < 2; na++)
#pragma unroll
            for (int q = 0; q < 4; q++) acc[ma][na][q] = 0.f;

#define ISSUE(ktv)                                                            \
    do {                                                                      \
        uint32_t s_ = sb + ((ktv) % NSTAGE) * STAGE_B;                        \
        int o_ = (ktv) * 32;                                                  \
        cp16(s_ + OFF_AH + dA0, gAh0 + o_);                                   \
        cp16(s_ + OFF_AH + dA1, gAh1 + o_);                                   \
        cp16(s_ + OFF_AL + dA0, gAl0 + o_);                                   \
        cp16(s_ + OFF_AL + dA1, gAl1 + o_);                                   \
        cp16(s_ + OFF_BH + dA0, gBh0 + o_);                                   \
        cp16(s_ + OFF_BL + dA0, gBl0 + o_);                                   \
    } while (0)

    ISSUE(0); CP_COMMIT();
    if (KT > 1) ISSUE(1);
    CP_COMMIT();

    for (int kt = 0; kt < KT; kt++) {
        CP_WAIT1();
        __syncthreads();
        const uint32_t bufb = sb + (kt % NSTAGE) * STAGE_B;
        const uint32_t aAh = bufb + OFF_AH, aAl = bufb + OFF_AL;
        const uint32_t aBh = bufb + OFF_BH, aBl = bufb + OFF_BL;

#pragma unroll
        for (int ss = 0; ss < 2; ss++) {
            uint32_t bhf[2][2], blf[2][2];
#pragma unroll
            for (int na = 0; na < 2; na++) {
                uint32_t boff = brow + na * 8 * ROWB + ss * 32;
                ldsm_x2(bhf[na], aBh + boff);
                ldsm_x2(blf[na], aBl + boff);
            }
#pragma unroll
            for (int ma = 0; ma < 4; ma++) {
                uint32_t ah[4], al[4];
                uint32_t aoff = arow + ma * 16 * ROWB + ss * 32;
                ldsm_x4(ah, aAh + aoff);
                ldsm_x4(al, aAl + aoff);
#pragma unroll
                for (int na = 0; na < 2; na++) {
                    mma16816(acc[ma][na], ah, bhf[na]);
                    mma16816(acc[ma][na], ah, blf[na]);
                    mma16816(acc[ma][na], al, bhf[na]);
                }
            }
        }

        if (kt + NSTAGE - 1 < KT) ISSUE(kt + NSTAGE - 1);
        CP_COMMIT();
    }
#undef ISSUE

    // ---- epilogue ----
    if (PARTIAL) {
        size_t cbase = (size_t)blockIdx.z * M * NC;
#pragma unroll
        for (int ma = 0; ma < 4; ma++) {
#pragma unroll
            for (int na = 0; na < 2; na++) {
                int r0 = u0 + wm * 64 + ma * 16 + (lane >> 2);
                int c  = j0 + wn * 16 + na * 8 + (lane & 3) * 2;
                *(float2*)(Cp + cbase + (size_t)r0 * NC + c) =
                    make_float2(acc[ma][na][0], acc[ma][na][1]);
                *(float2*)(Cp + cbase + (size_t)(r0 + 8) * NC + c) =
                    make_float2(acc[ma][na][2], acc[ma][na][3]);
            }
        }
    } else {
        // drain pipeline before reusing stage smem for C staging
        CP_WAIT0();
        __syncthreads();
        float* sC = (float*)dsm;        // [128][CSTR]
#pragma unroll
        for (int ma = 0; ma < 4; ma++) {
#pragma unroll
            for (int na = 0; na < 2; na++) {
                int lr = wm * 64 + ma * 16 + (lane >> 2);
                int lc = wn * 16 + na * 8 + (lane & 3) * 2;
                int r0 = u0 + lr;
                int c  = j0 + lc;
                size_t o0 = (size_t)r0 * NC + c;
                size_t o1 = (size_t)(r0 + 8) * NC + c;
                float2 v0 = make_float2(s2 * acc[ma][na][0], s2 * acc[ma][na][1]);
                float2 v1 = make_float2(s2 * acc[ma][na][2], s2 * acc[ma][na][3]);
                if (hasA) {
                    float2 a0 = *(const float2*)(Ap + o0);
                    float2 a1 = *(const float2*)(Ap + o1);
                    v0.x -= a0.x; v0.y -= a0.y;
                    v1.x -= a1.x; v1.y -= a1.y;
                }
                *(float2*)(Cp + o0) = v0;
                *(float2*)(Cp + o1) = v1;
                sC[lr * CSTR + lc] = v0.x;
                sC[lr * CSTR + lc + 1] = v0.y;
                sC[(lr + 8) * CSTR + lc] = v1.x;
                sC[(lr + 8) * CSTR + lc + 1] = v1.y;
            }
        }
        if (doSplit) {
            __syncthreads();
            int j  = tid >> 2;              // 0..63
            int vq = (tid & 3) * 32;        // 0/32/64/96
            uint32_t* oh = (uint32_t*)(Ho + (size_t)(j0 + j) * M + u0 + vq);
            uint32_t* ol = (uint32_t*)(Lo + (size_t)(j0 + j) * M + u0 + vq);
#pragma unroll
            for (int m = 0; m < 16; m++) {
                float a = sC[(vq + 2 * m) * CSTR + j];
                float b = sC[(vq + 2 * m + 1) * CSTR + j];
                uint32_t h2, l2;
                split2(a, b, h2, l2);
                oh[m] = h2;
                ol[m] = l2;
            }
        }
    }
}

// ---------------------------------------------------------------------------
// Layer1 tail: relu(maxpool4(T1 @ W1) + b1) -> layer2 state 0
// ---------------------------------------------------------------------------
__global__ __launch_bounds__(256)
void layer1_pool(const float* __restrict__ W1, const float* __restrict__ b1)
{
    __shared__ float W1s[K_CHEB * F0];
    __shared__ float b1s[F0];
    int n   = threadIdx.x;
    int u1  = blockIdx.x * 4 + threadIdx.y;
    int tid = threadIdx.y * 64 + n;

    for (int i = tid; i < K_CHEB * F0; i += 256) W1s[i] = W1[i];
    if (tid < F0) b1s[tid] = b1[tid];
    __syncthreads();

    float m[F0];
#pragma unroll
    for (int f = 0; f < F0; f++) m[f] = -1e30f;

    for (int p = 0; p < 4; p++) {
        float acc[F0];
#pragma unroll
        for (int f = 0; f < F0; f++) acc[f] = 0.f;
        int u = u1 * 4 + p;
        const float* tp = g_T1 + (size_t)u * NC1 + n;
        for (int k = 0; k < K_CHEB; k++) {
            float t = tp[(size_t)k * SL1];
#pragma unroll
            for (int f = 0; f < F0; f++) acc[f] += t * W1s[k * F0 + f];
        }
#pragma unroll
        for (int f = 0; f < F0; f++) m[f] = fmaxf(m[f], acc[f]);
    }
    float* op = g_T2 + (size_t)u1 * NC2 + n * F0;
#pragma unroll
    for (int f = 0; f < F0; f++) op[f] = fmaxf(m[f] + b1s[f], 0.f);
}

// ---------------------------------------------------------------------------
// Layer2 tail: OUT2 = relu(maxpool4(T2_features @ W2) + b2)
// ---------------------------------------------------------------------------
__global__ __launch_bounds__(128)
void layer2_pool(const float* __restrict__ W2, const float* __restrict__ b2)
{
    extern __shared__ float Wall[];
    int n   = threadIdx.x;
    int u1  = blockIdx.x * 2 + threadIdx.y;
    int f0  = blockIdx.y * 32;
    int tid = threadIdx.y * 64 + n;

    for (int i = tid; i < 800 * 32; i += 128) {
        int r = i >> 5, f = i & 31;
        Wall[i] = W2[(size_t)r * F1 + f0 + f];
    }
    __syncthreads();

    float m[32];
#pragma unroll
    for (int f = 0; f < 32; f++) m[f] = -1e30f;

    for (int p = 0; p < 4; p++) {
        float acc[32];
#pragma unroll
        for (int f = 0; f < 32; f++) acc[f] = 0.f;
        int u = u1 * 4 + p;
        for (int k = 0; k < K_CHEB; k++) {
            const float4* tp = (const float4*)(g_T2 + (size_t)k * SL2 +
                                               (size_t)u * NC2 + n * F0);
#pragma unroll
            for (int c4 = 0; c4 < 8; c4++) {
                float4 t = tp[c4];
                const float* w0 = &Wall[((c4 * 4 + 0) * K_CHEB + k) * 32];
                const float* w1 = &Wall[((c4 * 4 + 1) * K_CHEB + k) * 32];
                const float* w2 = &Wall[((c4 * 4 + 2) * K_CHEB + k) * 32];
                const float* w3 = &Wall[((c4 * 4 + 3) * K_CHEB + k) * 32];
#pragma unroll
                for (int f = 0; f < 32; f++) {
                    acc[f] += t.x * w0[f];
                    acc[f] += t.y * w1[f];
                    acc[f] += t.z * w2[f];
                    acc[f] += t.w * w3[f];
                }
            }
        }
#pragma unroll
        for (int f = 0; f < 32; f++) m[f] = fmaxf(m[f], acc[f]);
    }
    float* op = g_OUT2 + (size_t)n * 16384 + u1 * F1 + f0;
#pragma unroll
    for (int f = 0; f < 32; f++) op[f] = fmaxf(m[f] + b2[f0 + f], 0.f);
}

// ---------------------------------------------------------------------------
// FC head
// ---------------------------------------------------------------------------
__global__ __launch_bounds__(256)
void fc1_partial(const float* __restrict__ Wh)
{
    __shared__ float As[32][68];
    __shared__ float Ws[32][32];
    int tid  = threadIdx.x;
    int j0   = blockIdx.x * 32;
    int kz   = blockIdx.y * 2048;
    int tcol = tid & 31;
    int n0   = (tid >> 5) * 8;
    float acc[8];
#pragma unroll
    for (int i = 0; i < 8; i++) acc[i] = 0.f;

    for (int k0 = 0; k0 < 2048; k0 += 32) {
        __syncthreads();
#pragma unroll
        for (int it = 0; it < 2; it++) {
            int idx = tid * 4 + it * 1024;
            int nn = idx >> 5;
            int kk = idx & 31;
            float4 v = *(const float4*)(g_OUT2 + (size_t)nn * 16384 + kz + k0 + kk);
            As[kk + 0][nn] = v.x; As[kk + 1][nn] = v.y;
            As[kk + 2][nn] = v.z; As[kk + 3][nn] = v.w;
        }
#pragma unroll
        for (int i = tid; i < 1024; i += 256) {
            int r = i >> 5, c = i & 31;
            Ws[r][c] = Wh[(size_t)(kz + k0 + r) * 512 + j0 + c];
        }
        __syncthreads();
#pragma unroll
        for (int kk = 0; kk < 32; kk++) {
            float w = Ws[kk][tcol];
            float4 a0 = *(const float4*)&As[kk][n0];
            float4 a1 = *(const float4*)&As[kk][n0 + 4];
            acc[0] += a0.x * w; acc[1] += a0.y * w;
            acc[2] += a0.z * w; acc[3] += a0.w * w;
            acc[4] += a1.x * w; acc[5] += a1.y * w;
            acc[6] += a1.z * w; acc[7] += a1.w * w;
        }
    }
#pragma unroll
    for (int i = 0; i < 8; i++)
        g_P[(size_t)blockIdx.y * 32768 + (size_t)(n0 + i) * 512 + j0 + tcol] = acc[i];
}

__global__ void fc1_reduce(const float* __restrict__ bh)
{
    int i = blockIdx.x * blockDim.x + threadIdx.x;
    float s = 0.f;
#pragma unroll
    for (int z = 0; z < 8; z++) s += g_P[(size_t)z * 32768 + i];
    g_Yh[i] = fmaxf(s + bh[i & 511], 0.f);
}

__global__ void fc2(const float* __restrict__ Wo, const float* __restrict__ bo,
                    float* __restrict__ out)
{
    int g = blockIdx.x * blockDim.x + threadIdx.x;
    if (g >= 640) return;
    int n = g / 10, o = g % 10;
    float s = bo[o];
    const float* y = g_Yh + (size_t)n * 512;
    for (int j = 0; j < 512; j++) s += y[j] * Wo[j * 10 + o];
    out[g] = s;
}

// ---------------------------------------------------------------------------
// Host driver
// ---------------------------------------------------------------------------
extern "C" void kernel_launch(void* const* d_in, const int* in_sizes, int n_in,
                              void* d_out, int out_size)
{
    const float* x  = (const float*)d_in[0];
    const float* L0 = (const float*)d_in[1];
    const float* L1 = (const float*)d_in[2];
    const float* W1 = (const float*)d_in[3];
    const float* b1 = (const float*)d_in[4];
    const float* W2 = (const float*)d_in[5];
    const float* b2 = (const float*)d_in[6];
    const float* Wh = (const float*)d_in[7];
    const float* bh = (const float*)d_in[8];
    const float* Wo = (const float*)d_in[9];
    const float* bo = (const float*)d_in[10];
    float* out = (float*)d_out;

    float *T1p, *T2p, *PZp;
    __nv_bfloat16 *L0h, *L0l, *L1h, *L1l, *Bh1, *Bl1, *Bh2, *Bl2;
    cudaGetSymbolAddress((void**)&T1p, g_T1);
    cudaGetSymbolAddress((void**)&T2p, g_T2);
    cudaGetSymbolAddress((void**)&PZp, g_PZ);
    cudaGetSymbolAddress((void**)&L0h, g_L0h);
    cudaGetSymbolAddress((void**)&L0l, g_L0l);
    cudaGetSymbolAddress((void**)&L1h, g_L1h);
    cudaGetSymbolAddress((void**)&L1l, g_L1l);
    cudaGetSymbolAddress((void**)&Bh1, g_Bh1);
    cudaGetSymbolAddress((void**)&Bl1, g_Bl1);
    cudaGetSymbolAddress((void**)&Bh2, g_Bh2);
    cudaGetSymbolAddress((void**)&Bl2, g_Bl2);
    const size_t BSL2 = (size_t)NC2 * M1;

    const int GEMM_SMEM = NSTAGE * STAGE_B;   // 92160
    cudaFuncSetAttribute(cheb_gemm_mma<0>,
                         cudaFuncAttributeMaxDynamicSharedMemorySize, GEMM_SMEM);
    cudaFuncSetAttribute(cheb_gemm_mma<1>,
                         cudaFuncAttributeMaxDynamicSharedMemorySize, GEMM_SMEM);

    // ---- prep: split L matrices into bf16 hi/lo ----
    split_bf16<<<(M0 * M0 / 4 + 255) / 256, 256>>>(L0, L0h, L0l, M0 * M0 / 4);
    split_bf16<<<(M1 * M1 / 4 + 255) / 256, 256>>>(L1, L1h, L1l, M1 * M1 / 4);

    // ---- layer 1 Chebyshev recurrence ----
    transpose_x<<<dim3(M0 / 32, N_BATCH / 32), dim3(32, 8)>>>(x, T1p);
    // T0 transposed = x itself -> direct split, no transpose needed
    split_bf16<<<SL1 / 4 / 256, 256>>>(x, Bh1, Bl1, SL1 / 4);

    for (int k = 1; k < K_CHEB; k++) {
        cheb_gemm_mma<1><<<dim3(1, M0 / 128, Z1), 256, GEMM_SMEM>>>(
            L0h, L0l, Bh1, Bl1, nullptr, PZp, nullptr, nullptr,
            M0, NC1, KZ1, 0.f, 0, 0);
        combine_split<<<dim3(M0 / 64, NC1 / 32), dim3(32, 8)>>>(
            (k >= 2) ? T1p + (size_t)(k - 2) * SL1 : nullptr,
            T1p + (size_t)k * SL1, Bh1, Bl1,
            (k == 1) ? 1.f : 2.f, (k >= 2) ? 1 : 0);
    }

    // ---- layer 1 contraction + relu + pool -> layer2 state 0 ----
    layer1_pool<<<M1, dim3(64, 4)>>>(W1, b1);

    // ---- layer 2 Chebyshev recurrence (split fused into GEMM epilogue) ----
    split_trans<<<dim3(M1 / 64, NC2 / 32), dim3(32, 8)>>>(
        T2p, Bh2, Bl2, M1, NC2);               // buf 0 <- T_0
    for (int k = 1; k < K_CHEB; k++) {
        int rb = (k - 1) & 1, wb = k & 1;
        cheb_gemm_mma<0><<<dim3(NC2 / 64, M1 / 128, 1), 256, GEMM_SMEM>>>(
            L1h, L1l, Bh2 + (size_t)rb * BSL2, Bl2 + (size_t)rb * BSL2,
            (k >= 2) ? T2p + (size_t)(k - 2) * SL2 : nullptr,
            T2p + (size_t)k * SL2,
            Bh2 + (size_t)wb * BSL2, Bl2 + (size_t)wb * BSL2,
            M1, NC2, M1, (k == 1) ? 1.f : 2.f, (k >= 2) ? 1 : 0,
            (k < K_CHEB - 1) ? 1 : 0);
    }

    // ---- layer 2 contraction + relu + pool ----
    cudaFuncSetAttribute(layer2_pool, cudaFuncAttributeMaxDynamicSharedMemorySize,
                         800 * 32 * 4);
    layer2_pool<<<dim3(128, 2), dim3(64, 2), 800 * 32 * 4>>>(W2, b2);

    // ---- FC head ----
    fc1_partial<<<dim3(16, 8), 256>>>(Wh);
    fc1_reduce<<<128, 256>>>(bh);
    fc2<<<5, 128>>>(Wo, bo, out);
}

// round 13
// speedup vs baseline: 1.5729x; 1.5729x over previous
#include <cuda_runtime.h>
#include <cuda_bf16.h>
#include <cstdint>
#include <cstddef>

// ---------------------------------------------------------------------------
// Problem constants
// ---------------------------------------------------------------------------
#define N_BATCH 64
#define M0 4096
#define M1 1024
#define K_CHEB 25
#define F0 32
#define F1 64
#define NC1 64
#define NC2 2048
#define SL1 (M0*NC1)
#define SL2 (M1*NC2)
#define Z1 8
#define KZ1 (M0/Z1)     // 512

// ---------------------------------------------------------------------------
// Device scratch
// ---------------------------------------------------------------------------
__device__ float g_T1[K_CHEB * SL1];
__device__ float g_T2[(size_t)K_CHEB * SL2];
__device__ float g_PZ[(size_t)Z1 * SL1];
__device__ float g_OUT2[N_BATCH * 16384];
__device__ float g_P[8 * N_BATCH * 512];
__device__ float g_Yh[N_BATCH * 512];
__device__ __nv_bfloat16 g_L0h[(size_t)M0 * M0];
__device__ __nv_bfloat16 g_L0l[(size_t)M0 * M0];
__device__ __nv_bfloat16 g_L1h[(size_t)M1 * M1];
__device__ __nv_bfloat16 g_L1l[(size_t)M1 * M1];
// pre-split, pre-transposed state buffers: [j][v] (N-major)
__device__ __nv_bfloat16 g_Bh1[(size_t)NC1 * M0];
__device__ __nv_bfloat16 g_Bl1[(size_t)NC1 * M0];
__device__ __nv_bfloat16 g_Bh2[(size_t)NC2 * M1];
__device__ __nv_bfloat16 g_Bl2[(size_t)NC2 * M1];

// ---------------------------------------------------------------------------
// MMA / async-copy helpers (portable Ampere-era ops)
// ---------------------------------------------------------------------------
__device__ __forceinline__ uint32_t smem_u32(const void* p) {
    uint32_t a;
    asm("{ .reg .u64 t; cvta.to.shared.u64 t, %1; cvt.u32.u64 %0, t; }"
        : "=r"(a) : "l"(p));
    return a;
}
__device__ __forceinline__ void ldsm_x4(uint32_t* r, uint32_t addr) {
    asm volatile("ldmatrix.sync.aligned.m8n8.x4.shared.b16 {%0,%1,%2,%3}, [%4];"
        : "=r"(r[0]), "=r"(r[1]), "=r"(r[2]), "=r"(r[3]) : "r"(addr));
}
__device__ __forceinline__ void ldsm_x2(uint32_t* r, uint32_t addr) {
    asm volatile("ldmatrix.sync.aligned.m8n8.x2.shared.b16 {%0,%1}, [%2];"
        : "=r"(r[0]), "=r"(r[1]) : "r"(addr));
}
__device__ __forceinline__ void mma16816(float* c, const uint32_t* a,
                                         const uint32_t* b) {
    asm volatile(
        "mma.sync.aligned.m16n8k16.row.col.f32.bf16.bf16.f32 "
        "{%0,%1,%2,%3}, {%4,%5,%6,%7}, {%8,%9}, {%0,%1,%2,%3};"
        : "+f"(c[0]), "+f"(c[1]), "+f"(c[2]), "+f"(c[3])
        : "r"(a[0]), "r"(a[1]), "r"(a[2]), "r"(a[3]), "r"(b[0]), "r"(b[1]));
}
__device__ __forceinline__ void cp16(uint32_t saddr, const void* g) {
    asm volatile("cp.async.cg.shared.global [%0], [%1], 16;"
        :: "r"(saddr), "l"(g) : "memory");
}
#define CP_COMMIT() asm volatile("cp.async.commit_group;" ::: "memory")
#define CP_WAIT1()  asm volatile("cp.async.wait_group 1;" ::: "memory")

__device__ __forceinline__ void split2(float a, float b, uint32_t& h2, uint32_t& l2)
{
    __nv_bfloat16 ha = __float2bfloat16(a), hb = __float2bfloat16(b);
    float ra = __bfloat162float(ha), rb = __bfloat162float(hb);
    __nv_bfloat16 la = __float2bfloat16(a - ra), lb = __float2bfloat16(b - rb);
    h2 = (uint32_t)__bfloat16_as_ushort(ha) | ((uint32_t)__bfloat16_as_ushort(hb) << 16);
    l2 = (uint32_t)__bfloat16_as_ushort(la) | ((uint32_t)__bfloat16_as_ushort(lb) << 16);
}

// ---------------------------------------------------------------------------
// Prep: split fp32 matrix -> bf16 hi/lo (same layout)
// ---------------------------------------------------------------------------
__global__ void split_bf16(const float* __restrict__ src,
                           __nv_bfloat16* __restrict__ hi,
                           __nv_bfloat16* __restrict__ lo, int n4)
{
    int i = blockIdx.x * blockDim.x + threadIdx.x;
    if (i >= n4) return;
    float4 v = ((const float4*)src)[i];
    uint32_t h0, l0, h1, l1;
    split2(v.x, v.y, h0, l0);
    split2(v.z, v.w, h1, l1);
    ((uint2*)hi)[i] = make_uint2(h0, h1);
    ((uint2*)lo)[i] = make_uint2(l0, l1);
}

// ---------------------------------------------------------------------------
// split_trans: fp32 state X[M rows][NC cols] -> bf16 hi/lo transposed [NC][M]
// (layer2 per-step state conversion)
// ---------------------------------------------------------------------------
__global__ __launch_bounds__(256)
void split_trans(const float* __restrict__ X,
                 __nv_bfloat16* __restrict__ Hi,
                 __nv_bfloat16* __restrict__ Lo, int M, int NC)
{
    __shared__ float s[64][33];
    int m0 = blockIdx.x * 64, nc0 = blockIdx.y * 32;
    int tx = threadIdx.x, ty = threadIdx.y;
    for (int r = ty; r < 64; r += 8)
        s[r][tx] = X[(size_t)(m0 + r) * NC + nc0 + tx];
    __syncthreads();
    for (int r = ty; r < 32; r += 8) {
        int j = nc0 + r;
        float a = s[tx * 2][r], b = s[tx * 2 + 1][r];
        uint32_t h2, l2;
        split2(a, b, h2, l2);
        ((uint32_t*)(Hi + (size_t)j * M + m0))[tx] = h2;
        ((uint32_t*)(Lo + (size_t)j * M + m0))[tx] = l2;
    }
}

// ---------------------------------------------------------------------------
// combine_split (layer1): C = s2*sum_z PZ - hasA*A  (fp32 [u][n]),
// plus transposed bf16 hi/lo [n][u] for the next GEMM's B.
// Tile 64 u x 32 n, block (32,8), grid (M0/64, NC1/32).
// ---------------------------------------------------------------------------
__global__ __launch_bounds__(256)
void combine_split(const float* __restrict__ Ap, float* __restrict__ Cp,
                   __nv_bfloat16* __restrict__ Hi, __nv_bfloat16* __restrict__ Lo,
                   float s2, int hasA)
{
    __shared__ float s[64][33];
    int m0 = blockIdx.x * 64, nc0 = blockIdx.y * 32;
    int tx = threadIdx.x, ty = threadIdx.y;
    for (int r = ty; r < 64; r += 8) {
        size_t off = (size_t)(m0 + r) * NC1 + nc0 + tx;
        float acc = 0.f;
#pragma unroll
        for (int z = 0; z < Z1; z++)
            acc += g_PZ[(size_t)z * SL1 + off];
        float c = s2 * acc;
        if (hasA) c -= Ap[off];
        Cp[off] = c;
        s[r][tx] = c;
    }
    __syncthreads();
    for (int r = ty; r < 32; r += 8) {
        int j = nc0 + r;
        uint32_t h2, l2;
        split2(s[tx * 2][r], s[tx * 2 + 1][r], h2, l2);
        ((uint32_t*)(Hi + (size_t)j * M0 + m0))[tx] = h2;
        ((uint32_t*)(Lo + (size_t)j * M0 + m0))[tx] = l2;
    }
}

// ---------------------------------------------------------------------------
// Transpose x (N,4096) -> T1 slab 0 as [u][n]
// ---------------------------------------------------------------------------
__global__ void transpose_x(const float* __restrict__ x, float* __restrict__ T0)
{
    __shared__ float s[32][33];
    int u0 = blockIdx.x * 32, n0 = blockIdx.y * 32;
    int tx = threadIdx.x, ty = threadIdx.y;
    for (int r = ty; r < 32; r += 8)
        s[r][tx] = x[(size_t)(n0 + r) * M0 + u0 + tx];
    __syncthreads();
    for (int r = ty; r < 32; r += 8)
        T0[(size_t)(u0 + r) * NC1 + n0 + tx] = s[tx][r];
}

// ---------------------------------------------------------------------------
// Tensor-core (mma.sync) Chebyshev GEMM, 128x64 CTA tile, 256 threads,
// cp.async 3-stage pipeline.  (identical to round-10 hot kernel)
//   PARTIAL=1: raw D -> Cp slab blockIdx.z.  PARTIAL=0: C = s2*D - hasA*A.
// ---------------------------------------------------------------------------
#define ROWB   80
#define OFF_AH 0
#define OFF_AL 10240
#define OFF_BH 20480
#define OFF_BL 25600
#define STAGE_B 30720
#define NSTAGE 3

template<int PARTIAL>
__global__ __launch_bounds__(256)
void cheb_gemm_mma(const __nv_bfloat16* __restrict__ Lh,
                   const __nv_bfloat16* __restrict__ Ll,
                   const __nv_bfloat16* __restrict__ Bh,
                   const __nv_bfloat16* __restrict__ Bl,
                   const float* __restrict__ Ap,
                   float* __restrict__ Cp,
                   int M, int NC, int KLEN, float s2, int hasA)
{
    extern __shared__ __align__(16) char dsm[];
    const uint32_t sb = smem_u32(dsm);

    const int tid  = threadIdx.x;
    const int lane = tid & 31;
    const int wid  = tid >> 5;
    const int wm   = wid & 1;
    const int wn   = wid >> 1;
    const int u0   = blockIdx.y * 128;
    const int j0   = blockIdx.x * 64;
    const int kz   = blockIdx.z * KLEN;
    const int KT   = KLEN >> 5;

    const int ar0  = tid >> 2;
    const int ar1  = ar0 + 64;
    const int ac16 = (tid & 3) * 16;
    const int acol = (tid & 3) * 8;

    const __nv_bfloat16* gAh0 = Lh + (size_t)(u0 + ar0) * M + kz + acol;
    const __nv_bfloat16* gAh1 = Lh + (size_t)(u0 + ar1) * M + kz + acol;
    const __nv_bfloat16* gAl0 = Ll + (size_t)(u0 + ar0) * M + kz + acol;
    const __nv_bfloat16* gAl1 = Ll + (size_t)(u0 + ar1) * M + kz + acol;
    const __nv_bfloat16* gBh0 = Bh + (size_t)(j0 + ar0) * M + kz + acol;
    const __nv_bfloat16* gBl0 = Bl + (size_t)(j0 + ar0) * M + kz + acol;

    const uint32_t dA0 = ar0 * ROWB + ac16;
    const uint32_t dA1 = ar1 * ROWB + ac16;

    const uint32_t arow = (uint32_t)((wm * 64 + (lane & 15)) * ROWB
                                     + (lane >> 4) * 16);
    const uint32_t brow = (uint32_t)((wn * 16 + (lane & 7)) * ROWB
                                     + ((lane >> 3) & 1) * 16);

    float acc[4][2][4];
#pragma unroll
    for (int ma = 0; ma < 4; ma++)
#pragma unroll
        for (int na = 0; na < 2; na++)
#pragma unroll
            for (int q = 0; q < 4; q++) acc[ma][na][q] = 0.f;

#define ISSUE(ktv)                                                            \
    do {                                                                      \
        uint32_t s_ = sb + ((ktv) % NSTAGE) * STAGE_B;                        \
        int o_ = (ktv) * 32;                                                  \
        cp16(s_ + OFF_AH + dA0, gAh0 + o_);                                   \
        cp16(s_ + OFF_AH + dA1, gAh1 + o_);                                   \
        cp16(s_ + OFF_AL + dA0, gAl0 + o_);                                   \
        cp16(s_ + OFF_AL + dA1, gAl1 + o_);                                   \
        cp16(s_ + OFF_BH + dA0, gBh0 + o_);                                   \
        cp16(s_ + OFF_BL + dA0, gBl0 + o_);                                   \
    } while (0)

    ISSUE(0); CP_COMMIT();
    if (KT > 1) ISSUE(1);
    CP_COMMIT();

    for (int kt = 0; kt < KT; kt++) {
        CP_WAIT1();
        __syncthreads();
        const uint32_t bufb = sb + (kt % NSTAGE) * STAGE_B;
        const uint32_t aAh = bufb + OFF_AH, aAl = bufb + OFF_AL;
        const uint32_t aBh = bufb + OFF_BH, aBl = bufb + OFF_BL;

#pragma unroll
        for (int ss = 0; ss < 2; ss++) {
            uint32_t bhf[2][2], blf[2][2];
#pragma unroll
            for (int na = 0; na < 2; na++) {
                uint32_t boff = brow + na * 8 * ROWB + ss * 32;
                ldsm_x2(bhf[na], aBh + boff);
                ldsm_x2(blf[na], aBl + boff);
            }
#pragma unroll
            for (int ma = 0; ma < 4; ma++) {
                uint32_t ah[4], al[4];
                uint32_t aoff = arow + ma * 16 * ROWB + ss * 32;
                ldsm_x4(ah, aAh + aoff);
                ldsm_x4(al, aAl + aoff);
#pragma unroll
                for (int na = 0; na < 2; na++) {
                    mma16816(acc[ma][na], ah, bhf[na]);
                    mma16816(acc[ma][na], ah, blf[na]);
                    mma16816(acc[ma][na], al, bhf[na]);
                }
            }
        }

        if (kt + NSTAGE - 1 < KT) ISSUE(kt + NSTAGE - 1);
        CP_COMMIT();
    }
#undef ISSUE

    // ---- epilogue ----
    size_t cbase = PARTIAL ? (size_t)blockIdx.z * M * NC : 0;
#pragma unroll
    for (int ma = 0; ma < 4; ma++) {
#pragma unroll
        for (int na = 0; na < 2; na++) {
            int r0 = u0 + wm * 64 + ma * 16 + (lane >> 2);
            int c  = j0 + wn * 16 + na * 8 + (lane & 3) * 2;
            size_t o0 = (size_t)r0 * NC + c;
            size_t o1 = (size_t)(r0 + 8) * NC + c;
            float2 v0 = make_float2(acc[ma][na][0], acc[ma][na][1]);
            float2 v1 = make_float2(acc[ma][na][2], acc[ma][na][3]);
            if (PARTIAL) {
                *(float2*)(Cp + cbase + o0) = v0;
                *(float2*)(Cp + cbase + o1) = v1;
            } else {
                v0.x *= s2; v0.y *= s2; v1.x *= s2; v1.y *= s2;
                if (hasA) {
                    float2 a0 = *(const float2*)(Ap + o0);
                    float2 a1 = *(const float2*)(Ap + o1);
                    v0.x -= a0.x; v0.y -= a0.y;
                    v1.x -= a1.x; v1.y -= a1.y;
                }
                *(float2*)(Cp + o0) = v0;
                *(float2*)(Cp + o1) = v1;
            }
        }
    }
}

// ---------------------------------------------------------------------------
// Layer1 tail: relu(maxpool4(T1 @ W1) + b1) -> layer2 state 0
// ---------------------------------------------------------------------------
__global__ __launch_bounds__(256)
void layer1_pool(const float* __restrict__ W1, const float* __restrict__ b1)
{
    __shared__ float W1s[K_CHEB * F0];
    __shared__ float b1s[F0];
    int n   = threadIdx.x;
    int u1  = blockIdx.x * 4 + threadIdx.y;
    int tid = threadIdx.y * 64 + n;

    for (int i = tid; i < K_CHEB * F0; i += 256) W1s[i] = W1[i];
    if (tid < F0) b1s[tid] = b1[tid];
    __syncthreads();

    float m[F0];
#pragma unroll
    for (int f = 0; f < F0; f++) m[f] = -1e30f;

    for (int p = 0; p < 4; p++) {
        float acc[F0];
#pragma unroll
        for (int f = 0; f < F0; f++) acc[f] = 0.f;
        int u = u1 * 4 + p;
        const float* tp = g_T1 + (size_t)u * NC1 + n;
        for (int k = 0; k < K_CHEB; k++) {
            float t = tp[(size_t)k * SL1];
#pragma unroll
            for (int f = 0; f < F0; f++) acc[f] += t * W1s[k * F0 + f];
        }
#pragma unroll
        for (int f = 0; f < F0; f++) m[f] = fmaxf(m[f], acc[f]);
    }
    float* op = g_T2 + (size_t)u1 * NC2 + n * F0;
#pragma unroll
    for (int f = 0; f < F0; f++) op[f] = fmaxf(m[f] + b1s[f], 0.f);
}

// ---------------------------------------------------------------------------
// Layer2 tail: OUT2 = relu(maxpool4(T2_features @ W2) + b2)
// ---------------------------------------------------------------------------
__global__ __launch_bounds__(128)
void layer2_pool(const float* __restrict__ W2, const float* __restrict__ b2)
{
    extern __shared__ float Wall[];
    int n   = threadIdx.x;
    int u1  = blockIdx.x * 2 + threadIdx.y;
    int f0  = blockIdx.y * 32;
    int tid = threadIdx.y * 64 + n;

    for (int i = tid; i < 800 * 32; i += 128) {
        int r = i >> 5, f = i & 31;
        Wall[i] = W2[(size_t)r * F1 + f0 + f];
    }
    __syncthreads();

    float m[32];
#pragma unroll
    for (int f = 0; f < 32; f++) m[f] = -1e30f;

    for (int p = 0; p < 4; p++) {
        float acc[32];
#pragma unroll
        for (int f = 0; f < 32; f++) acc[f] = 0.f;
        int u = u1 * 4 + p;
        for (int k = 0; k < K_CHEB; k++) {
            const float4* tp = (const float4*)(g_T2 + (size_t)k * SL2 +
                                               (size_t)u * NC2 + n * F0);
#pragma unroll
            for (int c4 = 0; c4 < 8; c4++) {
                float4 t = tp[c4];
                const float* w0 = &Wall[((c4 * 4 + 0) * K_CHEB + k) * 32];
                const float* w1 = &Wall[((c4 * 4 + 1) * K_CHEB + k) * 32];
                const float* w2 = &Wall[((c4 * 4 + 2) * K_CHEB + k) * 32];
                const float* w3 = &Wall[((c4 * 4 + 3) * K_CHEB + k) * 32];
#pragma unroll
                for (int f = 0; f < 32; f++) {
                    acc[f] += t.x * w0[f];
                    acc[f] += t.y * w1[f];
                    acc[f] += t.z * w2[f];
                    acc[f] += t.w * w3[f];
                }
            }
        }
#pragma unroll
        for (int f = 0; f < 32; f++) m[f] = fmaxf(m[f], acc[f]);
    }
    float* op = g_OUT2 + (size_t)n * 16384 + u1 * F1 + f0;
#pragma unroll
    for (int f = 0; f < 32; f++) op[f] = fmaxf(m[f] + b2[f0 + f], 0.f);
}

// ---------------------------------------------------------------------------
// FC head
// ---------------------------------------------------------------------------
__global__ __launch_bounds__(256)
void fc1_partial(const float* __restrict__ Wh)
{
    __shared__ float As[32][68];
    __shared__ float Ws[32][32];
    int tid  = threadIdx.x;
    int j0   = blockIdx.x * 32;
    int kz   = blockIdx.y * 2048;
    int tcol = tid & 31;
    int n0   = (tid >> 5) * 8;
    float acc[8];
#pragma unroll
    for (int i = 0; i < 8; i++) acc[i] = 0.f;

    for (int k0 = 0; k0 < 2048; k0 += 32) {
        __syncthreads();
#pragma unroll
        for (int it = 0; it < 2; it++) {
            int idx = tid * 4 + it * 1024;
            int nn = idx >> 5;
            int kk = idx & 31;
            float4 v = *(const float4*)(g_OUT2 + (size_t)nn * 16384 + kz + k0 + kk);
            As[kk + 0][nn] = v.x; As[kk + 1][nn] = v.y;
            As[kk + 2][nn] = v.z; As[kk + 3][nn] = v.w;
        }
#pragma unroll
        for (int i = tid; i < 1024; i += 256) {
            int r = i >> 5, c = i & 31;
            Ws[r][c] = Wh[(size_t)(kz + k0 + r) * 512 + j0 + c];
        }
        __syncthreads();
#pragma unroll
        for (int kk = 0; kk < 32; kk++) {
            float w = Ws[kk][tcol];
            float4 a0 = *(const float4*)&As[kk][n0];
            float4 a1 = *(const float4*)&As[kk][n0 + 4];
            acc[0] += a0.x * w; acc[1] += a0.y * w;
            acc[2] += a0.z * w; acc[3] += a0.w * w;
            acc[4] += a1.x * w; acc[5] += a1.y * w;
            acc[6] += a1.z * w; acc[7] += a1.w * w;
        }
    }
#pragma unroll
    for (int i = 0; i < 8; i++)
        g_P[(size_t)blockIdx.y * 32768 + (size_t)(n0 + i) * 512 + j0 + tcol] = acc[i];
}

__global__ void fc1_reduce(const float* __restrict__ bh)
{
    int i = blockIdx.x * blockDim.x + threadIdx.x;
    float s = 0.f;
#pragma unroll
    for (int z = 0; z < 8; z++) s += g_P[(size_t)z * 32768 + i];
    g_Yh[i] = fmaxf(s + bh[i & 511], 0.f);
}

__global__ void fc2(const float* __restrict__ Wo, const float* __restrict__ bo,
                    float* __restrict__ out)
{
    int g = blockIdx.x * blockDim.x + threadIdx.x;
    if (g >= 640) return;
    int n = g / 10, o = g % 10;
    float s = bo[o];
    const float* y = g_Yh + (size_t)n * 512;
    for (int j = 0; j < 512; j++) s += y[j] * Wo[j * 10 + o];
    out[g] = s;
}

// ---------------------------------------------------------------------------
// Host driver
// ---------------------------------------------------------------------------
extern "C" void kernel_launch(void* const* d_in, const int* in_sizes, int n_in,
                              void* d_out, int out_size)
{
    const float* x  = (const float*)d_in[0];
    const float* L0 = (const float*)d_in[1];
    const float* L1 = (const float*)d_in[2];
    const float* W1 = (const float*)d_in[3];
    const float* b1 = (const float*)d_in[4];
    const float* W2 = (const float*)d_in[5];
    const float* b2 = (const float*)d_in[6];
    const float* Wh = (const float*)d_in[7];
    const float* bh = (const float*)d_in[8];
    const float* Wo = (const float*)d_in[9];
    const float* bo = (const float*)d_in[10];
    float* out = (float*)d_out;

    float *T1p, *T2p, *PZp;
    __nv_bfloat16 *L0h, *L0l, *L1h, *L1l, *Bh1, *Bl1, *Bh2, *Bl2;
    cudaGetSymbolAddress((void**)&T1p, g_T1);
    cudaGetSymbolAddress((void**)&T2p, g_T2);
    cudaGetSymbolAddress((void**)&PZp, g_PZ);
    cudaGetSymbolAddress((void**)&L0h, g_L0h);
    cudaGetSymbolAddress((void**)&L0l, g_L0l);
    cudaGetSymbolAddress((void**)&L1h, g_L1h);
    cudaGetSymbolAddress((void**)&L1l, g_L1l);
    cudaGetSymbolAddress((void**)&Bh1, g_Bh1);
    cudaGetSymbolAddress((void**)&Bl1, g_Bl1);
    cudaGetSymbolAddress((void**)&Bh2, g_Bh2);
    cudaGetSymbolAddress((void**)&Bl2, g_Bl2);

    const int GEMM_SMEM = NSTAGE * STAGE_B;   // 92160
    cudaFuncSetAttribute(cheb_gemm_mma<0>,
                         cudaFuncAttributeMaxDynamicSharedMemorySize, GEMM_SMEM);
    cudaFuncSetAttribute(cheb_gemm_mma<1>,
                         cudaFuncAttributeMaxDynamicSharedMemorySize, GEMM_SMEM);

    // ---- prep: split L matrices into bf16 hi/lo ----
    split_bf16<<<(M0 * M0 / 4 + 255) / 256, 256>>>(L0, L0h, L0l, M0 * M0 / 4);
    split_bf16<<<(M1 * M1 / 4 + 255) / 256, 256>>>(L1, L1h, L1l, M1 * M1 / 4);

    // ---- layer 1 Chebyshev recurrence ----
    transpose_x<<<dim3(M0 / 32, N_BATCH / 32), dim3(32, 8)>>>(x, T1p);
    // T0 transposed = x itself -> direct split, no transpose needed
    split_bf16<<<SL1 / 4 / 256, 256>>>(x, Bh1, Bl1, SL1 / 4);

    for (int k = 1; k < K_CHEB; k++) {
        cheb_gemm_mma<1><<<dim3(1, M0 / 128, Z1), 256, GEMM_SMEM>>>(
            L0h, L0l, Bh1, Bl1, nullptr, PZp, M0, NC1, KZ1, 0.f, 0);
        combine_split<<<dim3(M0 / 64, NC1 / 32), dim3(32, 8)>>>(
            (k >= 2) ? T1p + (size_t)(k - 2) * SL1 : nullptr,
            T1p + (size_t)k * SL1, Bh1, Bl1,
            (k == 1) ? 1.f : 2.f, (k >= 2) ? 1 : 0);
    }

    // ---- layer 1 contraction + relu + pool -> layer2 state 0 ----
    layer1_pool<<<M1, dim3(64, 4)>>>(W1, b1);

    // ---- layer 2 Chebyshev recurrence (round-10 structure) ----
    for (int k = 1; k < K_CHEB; k++) {
        split_trans<<<dim3(M1 / 64, NC2 / 32), dim3(32, 8)>>>(
            T2p + (size_t)(k - 1) * SL2, Bh2, Bl2, M1, NC2);
        cheb_gemm_mma<0><<<dim3(NC2 / 64, M1 / 128, 1), 256, GEMM_SMEM>>>(
            L1h, L1l, Bh2, Bl2,
            (k >= 2) ? T2p + (size_t)(k - 2) * SL2 : nullptr,
            T2p + (size_t)k * SL2, M1, NC2, M1,
            (k == 1) ? 1.f : 2.f, (k >= 2) ? 1 : 0);
    }

    // ---- layer 2 contraction + relu + pool ----
    cudaFuncSetAttribute(layer2_pool, cudaFuncAttributeMaxDynamicSharedMemorySize,
                         800 * 32 * 4);
    layer2_pool<<<dim3(128, 2), dim3(64, 2), 800 * 32 * 4>>>(W2, b2);

    // ---- FC head ----
    fc1_partial<<<dim3(16, 8), 256>>>(Wh);
    fc1_reduce<<<128, 256>>>(bh);
    fc2<<<5, 128>>>(Wo, bo, out);
}

// round 14
// speedup vs baseline: 1.7630x; 1.1209x over previous
#include <cuda_runtime.h>
#include <cuda_bf16.h>
#include <cstdint>
#include <cstddef>

// ---------------------------------------------------------------------------
// Problem constants
// ---------------------------------------------------------------------------
#define N_BATCH 64
#define M0 4096
#define M1 1024
#define K_CHEB 25
#define F0 32
#define F1 64
#define NC1 64
#define NC2 2048
#define SL1 (M0*NC1)
#define SL2 (M1*NC2)
#define Z1 8
#define KZ1 (M0/Z1)     // 512

// ---------------------------------------------------------------------------
// Device scratch
// ---------------------------------------------------------------------------
__device__ float g_T1[K_CHEB * SL1];
__device__ float g_T2[(size_t)K_CHEB * SL2];
__device__ float g_PZ[(size_t)Z1 * SL1];
__device__ float g_OUT2[N_BATCH * 16384];
__device__ float g_P[8 * N_BATCH * 512];
__device__ float g_Yh[N_BATCH * 512];
__device__ __nv_bfloat16 g_L0h[(size_t)M0 * M0];
__device__ __nv_bfloat16 g_L0l[(size_t)M0 * M0];
__device__ __nv_bfloat16 g_L1h[(size_t)M1 * M1];
__device__ __nv_bfloat16 g_L1l[(size_t)M1 * M1];
// pre-split, pre-transposed state buffers: [j][v] (N-major)
__device__ __nv_bfloat16 g_Bh1[(size_t)NC1 * M0];
__device__ __nv_bfloat16 g_Bl1[(size_t)NC1 * M0];
__device__ __nv_bfloat16 g_Bh2[(size_t)NC2 * M1];
__device__ __nv_bfloat16 g_Bl2[(size_t)NC2 * M1];

// ---------------------------------------------------------------------------
// MMA / async-copy helpers (portable Ampere-era ops)
// ---------------------------------------------------------------------------
__device__ __forceinline__ uint32_t smem_u32(const void* p) {
    uint32_t a;
    asm("{ .reg .u64 t; cvta.to.shared.u64 t, %1; cvt.u32.u64 %0, t; }"
        : "=r"(a) : "l"(p));
    return a;
}
__device__ __forceinline__ void ldsm_x4(uint32_t* r, uint32_t addr) {
    asm volatile("ldmatrix.sync.aligned.m8n8.x4.shared.b16 {%0,%1,%2,%3}, [%4];"
        : "=r"(r[0]), "=r"(r[1]), "=r"(r[2]), "=r"(r[3]) : "r"(addr));
}
__device__ __forceinline__ void ldsm_x2(uint32_t* r, uint32_t addr) {
    asm volatile("ldmatrix.sync.aligned.m8n8.x2.shared.b16 {%0,%1}, [%2];"
        : "=r"(r[0]), "=r"(r[1]) : "r"(addr));
}
__device__ __forceinline__ void mma16816(float* c, const uint32_t* a,
                                         const uint32_t* b) {
    asm volatile(
        "mma.sync.aligned.m16n8k16.row.col.f32.bf16.bf16.f32 "
        "{%0,%1,%2,%3}, {%4,%5,%6,%7}, {%8,%9}, {%0,%1,%2,%3};"
        : "+f"(c[0]), "+f"(c[1]), "+f"(c[2]), "+f"(c[3])
        : "r"(a[0]), "r"(a[1]), "r"(a[2]), "r"(a[3]), "r"(b[0]), "r"(b[1]));
}
__device__ __forceinline__ void cp16(uint32_t saddr, const void* g) {
    asm volatile("cp.async.cg.shared.global [%0], [%1], 16;"
        :: "r"(saddr), "l"(g) : "memory");
}
#define CP_COMMIT() asm volatile("cp.async.commit_group;" ::: "memory")
#define CP_WAIT1()  asm volatile("cp.async.wait_group 1;" ::: "memory")

__device__ __forceinline__ void split2(float a, float b, uint32_t& h2, uint32_t& l2)
{
    __nv_bfloat16 ha = __float2bfloat16(a), hb = __float2bfloat16(b);
    float ra = __bfloat162float(ha), rb = __bfloat162float(hb);
    __nv_bfloat16 la = __float2bfloat16(a - ra), lb = __float2bfloat16(b - rb);
    h2 = (uint32_t)__bfloat16_as_ushort(ha) | ((uint32_t)__bfloat16_as_ushort(hb) << 16);
    l2 = (uint32_t)__bfloat16_as_ushort(la) | ((uint32_t)__bfloat16_as_ushort(lb) << 16);
}

// ---------------------------------------------------------------------------
// Prep: split fp32 matrix -> bf16 hi/lo (same layout)
// ---------------------------------------------------------------------------
__global__ void split_bf16(const float* __restrict__ src,
                           __nv_bfloat16* __restrict__ hi,
                           __nv_bfloat16* __restrict__ lo, int n4)
{
    int i = blockIdx.x * blockDim.x + threadIdx.x;
    if (i >= n4) return;
    float4 v = ((const float4*)src)[i];
    uint32_t h0, l0, h1, l1;
    split2(v.x, v.y, h0, l0);
    split2(v.z, v.w, h1, l1);
    ((uint2*)hi)[i] = make_uint2(h0, h1);
    ((uint2*)lo)[i] = make_uint2(l0, l1);
}

// ---------------------------------------------------------------------------
// split_trans: fp32 state X[M rows][NC cols] -> bf16 hi/lo transposed [NC][M]
// (layer2 per-step state conversion)
// ---------------------------------------------------------------------------
__global__ __launch_bounds__(256)
void split_trans(const float* __restrict__ X,
                 __nv_bfloat16* __restrict__ Hi,
                 __nv_bfloat16* __restrict__ Lo, int M, int NC)
{
    __shared__ float s[64][33];
    int m0 = blockIdx.x * 64, nc0 = blockIdx.y * 32;
    int tx = threadIdx.x, ty = threadIdx.y;
    for (int r = ty; r < 64; r += 8)
        s[r][tx] = X[(size_t)(m0 + r) * NC + nc0 + tx];
    __syncthreads();
    for (int r = ty; r < 32; r += 8) {
        int j = nc0 + r;
        float a = s[tx * 2][r], b = s[tx * 2 + 1][r];
        uint32_t h2, l2;
        split2(a, b, h2, l2);
        ((uint32_t*)(Hi + (size_t)j * M + m0))[tx] = h2;
        ((uint32_t*)(Lo + (size_t)j * M + m0))[tx] = l2;
    }
}

// ---------------------------------------------------------------------------
// combine_split (layer1): C = s2*sum_z PZ - hasA*A  (fp32 [u][n]),
// plus transposed bf16 hi/lo [n][u] for the next GEMM's B.
// ---------------------------------------------------------------------------
__global__ __launch_bounds__(256)
void combine_split(const float* __restrict__ Ap, float* __restrict__ Cp,
                   __nv_bfloat16* __restrict__ Hi, __nv_bfloat16* __restrict__ Lo,
                   float s2, int hasA)
{
    __shared__ float s[64][33];
    int m0 = blockIdx.x * 64, nc0 = blockIdx.y * 32;
    int tx = threadIdx.x, ty = threadIdx.y;
    for (int r = ty; r < 64; r += 8) {
        size_t off = (size_t)(m0 + r) * NC1 + nc0 + tx;
        float acc = 0.f;
#pragma unroll
        for (int z = 0; z < Z1; z++)
            acc += g_PZ[(size_t)z * SL1 + off];
        float c = s2 * acc;
        if (hasA) c -= Ap[off];
        Cp[off] = c;
        s[r][tx] = c;
    }
    __syncthreads();
    for (int r = ty; r < 32; r += 8) {
        int j = nc0 + r;
        uint32_t h2, l2;
        split2(s[tx * 2][r], s[tx * 2 + 1][r], h2, l2);
        ((uint32_t*)(Hi + (size_t)j * M0 + m0))[tx] = h2;
        ((uint32_t*)(Lo + (size_t)j * M0 + m0))[tx] = l2;
    }
}

// ---------------------------------------------------------------------------
// Transpose x (N,4096) -> T1 slab 0 as [u][n]
// ---------------------------------------------------------------------------
__global__ void transpose_x(const float* __restrict__ x, float* __restrict__ T0)
{
    __shared__ float s[32][33];
    int u0 = blockIdx.x * 32, n0 = blockIdx.y * 32;
    int tx = threadIdx.x, ty = threadIdx.y;
    for (int r = ty; r < 32; r += 8)
        s[r][tx] = x[(size_t)(n0 + r) * M0 + u0 + tx];
    __syncthreads();
    for (int r = ty; r < 32; r += 8)
        T0[(size_t)(u0 + r) * NC1 + n0 + tx] = s[tx][r];
}

// ---------------------------------------------------------------------------
// Tensor-core (mma.sync) Chebyshev GEMM, 128x64 CTA tile, 256 threads,
// cp.async 3-stage pipeline, SW64-swizzled smem (64B rows, no padding)
// -> stage 24576B, 3 stages = 73728B -> 3 CTAs/SM.
//   PARTIAL=1: raw D -> Cp slab blockIdx.z.  PARTIAL=0: C = s2*D - hasA*A.
// ---------------------------------------------------------------------------
#define OFF_AH 0
#define OFF_AL 8192
#define OFF_BH 16384
#define OFF_BL 20480
#define STAGE_B 24576
#define NSTAGE 3

template<int PARTIAL>
__global__ __launch_bounds__(256, 3)
void cheb_gemm_mma(const __nv_bfloat16* __restrict__ Lh,
                   const __nv_bfloat16* __restrict__ Ll,
                   const __nv_bfloat16* __restrict__ Bh,
                   const __nv_bfloat16* __restrict__ Bl,
                   const float* __restrict__ Ap,
                   float* __restrict__ Cp,
                   int M, int NC, int KLEN, float s2, int hasA)
{
    extern __shared__ __align__(16) char dsm[];
    const uint32_t sb = smem_u32(dsm);

    const int tid  = threadIdx.x;
    const int lane = tid & 31;
    const int wid  = tid >> 5;
    const int wm   = wid & 1;
    const int wn   = wid >> 1;
    const int u0   = blockIdx.y * 128;
    const int j0   = blockIdx.x * 64;
    const int kz   = blockIdx.z * KLEN;
    const int KT   = KLEN >> 5;

    // ---- loader indices (16B chunks, SW64 swizzle) ----
    const int ar0  = tid >> 2;            // row 0..63
    const int ch   = tid & 3;             // chunk 0..3
    const int sw0  = (tid >> 3) & 3;      // = (ar0>>1)&3
    const int acol = ch * 8;              // element offset in global row

    const __nv_bfloat16* gAh0 = Lh + (size_t)(u0 + ar0) * M + kz + acol;
    const __nv_bfloat16* gAh1 = Lh + (size_t)(u0 + ar0 + 64) * M + kz + acol;
    const __nv_bfloat16* gAl0 = Ll + (size_t)(u0 + ar0) * M + kz + acol;
    const __nv_bfloat16* gAl1 = Ll + (size_t)(u0 + ar0 + 64) * M + kz + acol;
    const __nv_bfloat16* gBh0 = Bh + (size_t)(j0 + ar0) * M + kz + acol;
    const __nv_bfloat16* gBl0 = Bl + (size_t)(j0 + ar0) * M + kz + acol;

    const uint32_t dA0 = (uint32_t)(ar0 * 64 + ((ch ^ sw0) * 16));
    const uint32_t dA1 = dA0 + 64 * 64;   // rows 64..127 (same swizzle phase)

    // ---- ldmatrix base offsets (SW64) ----
    const int swA = ((lane & 15) >> 1) & 3;
    const uint32_t arowb = (uint32_t)((wm * 64 + (lane & 15)) * 64);
    const uint32_t csA0 = (uint32_t)((((lane >> 4)) ^ swA) * 16);
    const uint32_t csA1 = (uint32_t)(((((lane >> 4)) + 2) ^ swA) * 16);
    const int swB = ((lane & 7) >> 1) & 3;
    const uint32_t browb = (uint32_t)((wn * 16 + (lane & 7)) * 64);
    const uint32_t csB0 = (uint32_t)(((((lane >> 3) & 1)) ^ swB) * 16);
    const uint32_t csB1 = (uint32_t)((((((lane >> 3) & 1)) + 2) ^ swB) * 16);

    float acc[4][2][4];
#pragma unroll
    for (int ma = 0; ma < 4; ma++)
#pragma unroll
        for (int na = 0; na < 2; na++)
#pragma unroll
            for (int q = 0; q < 4; q++) acc[ma][na][q] = 0.f;

#define ISSUE(ktv)                                                            \
    do {                                                                      \
        uint32_t s_ = sb + ((ktv) % NSTAGE) * STAGE_B;                        \
        int o_ = (ktv) * 32;                                                  \
        cp16(s_ + OFF_AH + dA0, gAh0 + o_);                                   \
        cp16(s_ + OFF_AH + dA1, gAh1 + o_);                                   \
        cp16(s_ + OFF_AL + dA0, gAl0 + o_);                                   \
        cp16(s_ + OFF_AL + dA1, gAl1 + o_);                                   \
        cp16(s_ + OFF_BH + dA0, gBh0 + o_);                                   \
        cp16(s_ + OFF_BL + dA0, gBl0 + o_);                                   \
    } while (0)

    ISSUE(0); CP_COMMIT();
    if (KT > 1) ISSUE(1);
    CP_COMMIT();

    for (int kt = 0; kt < KT; kt++) {
        CP_WAIT1();
        __syncthreads();
        const uint32_t bufb = sb + (kt % NSTAGE) * STAGE_B;
        const uint32_t aAh = bufb + OFF_AH, aAl = bufb + OFF_AL;
        const uint32_t aBh = bufb + OFF_BH, aBl = bufb + OFF_BL;

#pragma unroll
        for (int ss = 0; ss < 2; ss++) {
            const uint32_t csA = ss ? csA1 : csA0;
            const uint32_t csB = ss ? csB1 : csB0;
            uint32_t bhf[2][2], blf[2][2];
#pragma unroll
            for (int na = 0; na < 2; na++) {
                uint32_t boff = browb + na * 512 + csB;
                ldsm_x2(bhf[na], aBh + boff);
                ldsm_x2(blf[na], aBl + boff);
            }
#pragma unroll
            for (int ma = 0; ma < 4; ma++) {
                uint32_t ah[4], al[4];
                uint32_t aoff = arowb + ma * 1024 + csA;
                ldsm_x4(ah, aAh + aoff);
                ldsm_x4(al, aAl + aoff);
#pragma unroll
                for (int na = 0; na < 2; na++) {
                    mma16816(acc[ma][na], ah, bhf[na]);
                    mma16816(acc[ma][na], ah, blf[na]);
                    mma16816(acc[ma][na], al, bhf[na]);
                }
            }
        }

        if (kt + NSTAGE - 1 < KT) ISSUE(kt + NSTAGE - 1);
        CP_COMMIT();
    }
#undef ISSUE

    // ---- epilogue ----
    size_t cbase = PARTIAL ? (size_t)blockIdx.z * M * NC : 0;
#pragma unroll
    for (int ma = 0; ma < 4; ma++) {
#pragma unroll
        for (int na = 0; na < 2; na++) {
            int r0 = u0 + wm * 64 + ma * 16 + (lane >> 2);
            int c  = j0 + wn * 16 + na * 8 + (lane & 3) * 2;
            size_t o0 = (size_t)r0 * NC + c;
            size_t o1 = (size_t)(r0 + 8) * NC + c;
            float2 v0 = make_float2(acc[ma][na][0], acc[ma][na][1]);
            float2 v1 = make_float2(acc[ma][na][2], acc[ma][na][3]);
            if (PARTIAL) {
                *(float2*)(Cp + cbase + o0) = v0;
                *(float2*)(Cp + cbase + o1) = v1;
            } else {
                v0.x *= s2; v0.y *= s2; v1.x *= s2; v1.y *= s2;
                if (hasA) {
                    float2 a0 = *(const float2*)(Ap + o0);
                    float2 a1 = *(const float2*)(Ap + o1);
                    v0.x -= a0.x; v0.y -= a0.y;
                    v1.x -= a1.x; v1.y -= a1.y;
                }
                *(float2*)(Cp + o0) = v0;
                *(float2*)(Cp + o1) = v1;
            }
        }
    }
}

// ---------------------------------------------------------------------------
// Layer1 tail: relu(maxpool4(T1 @ W1) + b1) -> layer2 state 0
// ---------------------------------------------------------------------------
__global__ __launch_bounds__(256)
void layer1_pool(const float* __restrict__ W1, const float* __restrict__ b1)
{
    __shared__ float W1s[K_CHEB * F0];
    __shared__ float b1s[F0];
    int n   = threadIdx.x;
    int u1  = blockIdx.x * 4 + threadIdx.y;
    int tid = threadIdx.y * 64 + n;

    for (int i = tid; i < K_CHEB * F0; i += 256) W1s[i] = W1[i];
    if (tid < F0) b1s[tid] = b1[tid];
    __syncthreads();

    float m[F0];
#pragma unroll
    for (int f = 0; f < F0; f++) m[f] = -1e30f;

    for (int p = 0; p < 4; p++) {
        float acc[F0];
#pragma unroll
        for (int f = 0; f < F0; f++) acc[f] = 0.f;
        int u = u1 * 4 + p;
        const float* tp = g_T1 + (size_t)u * NC1 + n;
        for (int k = 0; k < K_CHEB; k++) {
            float t = tp[(size_t)k * SL1];
#pragma unroll
            for (int f = 0; f < F0; f++) acc[f] += t * W1s[k * F0 + f];
        }
#pragma unroll
        for (int f = 0; f < F0; f++) m[f] = fmaxf(m[f], acc[f]);
    }
    float* op = g_T2 + (size_t)u1 * NC2 + n * F0;
#pragma unroll
    for (int f = 0; f < F0; f++) op[f] = fmaxf(m[f] + b1s[f], 0.f);
}

// ---------------------------------------------------------------------------
// Layer2 tail: OUT2 = relu(maxpool4(T2_features @ W2) + b2)
// ---------------------------------------------------------------------------
__global__ __launch_bounds__(128)
void layer2_pool(const float* __restrict__ W2, const float* __restrict__ b2)
{
    extern __shared__ float Wall[];
    int n   = threadIdx.x;
    int u1  = blockIdx.x * 2 + threadIdx.y;
    int f0  = blockIdx.y * 32;
    int tid = threadIdx.y * 64 + n;

    for (int i = tid; i < 800 * 32; i += 128) {
        int r = i >> 5, f = i & 31;
        Wall[i] = W2[(size_t)r * F1 + f0 + f];
    }
    __syncthreads();

    float m[32];
#pragma unroll
    for (int f = 0; f < 32; f++) m[f] = -1e30f;

    for (int p = 0; p < 4; p++) {
        float acc[32];
#pragma unroll
        for (int f = 0; f < 32; f++) acc[f] = 0.f;
        int u = u1 * 4 + p;
        for (int k = 0; k < K_CHEB; k++) {
            const float4* tp = (const float4*)(g_T2 + (size_t)k * SL2 +
                                               (size_t)u * NC2 + n * F0);
#pragma unroll
            for (int c4 = 0; c4 < 8; c4++) {
                float4 t = tp[c4];
                const float* w0 = &Wall[((c4 * 4 + 0) * K_CHEB + k) * 32];
                const float* w1 = &Wall[((c4 * 4 + 1) * K_CHEB + k) * 32];
                const float* w2 = &Wall[((c4 * 4 + 2) * K_CHEB + k) * 32];
                const float* w3 = &Wall[((c4 * 4 + 3) * K_CHEB + k) * 32];
#pragma unroll
                for (int f = 0; f < 32; f++) {
                    acc[f] += t.x * w0[f];
                    acc[f] += t.y * w1[f];
                    acc[f] += t.z * w2[f];
                    acc[f] += t.w * w3[f];
                }
            }
        }
#pragma unroll
        for (int f = 0; f < 32; f++) m[f] = fmaxf(m[f], acc[f]);
    }
    float* op = g_OUT2 + (size_t)n * 16384 + u1 * F1 + f0;
#pragma unroll
    for (int f = 0; f < 32; f++) op[f] = fmaxf(m[f] + b2[f0 + f], 0.f);
}

// ---------------------------------------------------------------------------
// FC head
// ---------------------------------------------------------------------------
__global__ __launch_bounds__(256)
void fc1_partial(const float* __restrict__ Wh)
{
    __shared__ float As[32][68];
    __shared__ float Ws[32][32];
    int tid  = threadIdx.x;
    int j0   = blockIdx.x * 32;
    int kz   = blockIdx.y * 2048;
    int tcol = tid & 31;
    int n0   = (tid >> 5) * 8;
    float acc[8];
#pragma unroll
    for (int i = 0; i < 8; i++) acc[i] = 0.f;

    for (int k0 = 0; k0 < 2048; k0 += 32) {
        __syncthreads();
#pragma unroll
        for (int it = 0; it < 2; it++) {
            int idx = tid * 4 + it * 1024;
            int nn = idx >> 5;
            int kk = idx & 31;
            float4 v = *(const float4*)(g_OUT2 + (size_t)nn * 16384 + kz + k0 + kk);
            As[kk + 0][nn] = v.x; As[kk + 1][nn] = v.y;
            As[kk + 2][nn] = v.z; As[kk + 3][nn] = v.w;
        }
#pragma unroll
        for (int i = tid; i < 1024; i += 256) {
            int r = i >> 5, c = i & 31;
            Ws[r][c] = Wh[(size_t)(kz + k0 + r) * 512 + j0 + c];
        }
        __syncthreads();
#pragma unroll
        for (int kk = 0; kk < 32; kk++) {
            float w = Ws[kk][tcol];
            float4 a0 = *(const float4*)&As[kk][n0];
            float4 a1 = *(const float4*)&As[kk][n0 + 4];
            acc[0] += a0.x * w; acc[1] += a0.y * w;
            acc[2] += a0.z * w; acc[3] += a0.w * w;
            acc[4] += a1.x * w; acc[5] += a1.y * w;
            acc[6] += a1.z * w; acc[7] += a1.w * w;
        }
    }
#pragma unroll
    for (int i = 0; i < 8; i++)
        g_P[(size_t)blockIdx.y * 32768 + (size_t)(n0 + i) * 512 + j0 + tcol] = acc[i];
}

__global__ void fc1_reduce(const float* __restrict__ bh)
{
    int i = blockIdx.x * blockDim.x + threadIdx.x;
    float s = 0.f;
#pragma unroll
    for (int z = 0; z < 8; z++) s += g_P[(size_t)z * 32768 + i];
    g_Yh[i] = fmaxf(s + bh[i & 511], 0.f);
}

__global__ void fc2(const float* __restrict__ Wo, const float* __restrict__ bo,
                    float* __restrict__ out)
{
    int g = blockIdx.x * blockDim.x + threadIdx.x;
    if (g >= 640) return;
    int n = g / 10, o = g % 10;
    float s = bo[o];
    const float* y = g_Yh + (size_t)n * 512;
    for (int j = 0; j < 512; j++) s += y[j] * Wo[j * 10 + o];
    out[g] = s;
}

// ---------------------------------------------------------------------------
// Host driver
// ---------------------------------------------------------------------------
extern "C" void kernel_launch(void* const* d_in, const int* in_sizes, int n_in,
                              void* d_out, int out_size)
{
    const float* x  = (const float*)d_in[0];
    const float* L0 = (const float*)d_in[1];
    const float* L1 = (const float*)d_in[2];
    const float* W1 = (const float*)d_in[3];
    const float* b1 = (const float*)d_in[4];
    const float* W2 = (const float*)d_in[5];
    const float* b2 = (const float*)d_in[6];
    const float* Wh = (const float*)d_in[7];
    const float* bh = (const float*)d_in[8];
    const float* Wo = (const float*)d_in[9];
    const float* bo = (const float*)d_in[10];
    float* out = (float*)d_out;

    float *T1p, *T2p, *PZp;
    __nv_bfloat16 *L0h, *L0l, *L1h, *L1l, *Bh1, *Bl1, *Bh2, *Bl2;
    cudaGetSymbolAddress((void**)&T1p, g_T1);
    cudaGetSymbolAddress((void**)&T2p, g_T2);
    cudaGetSymbolAddress((void**)&PZp, g_PZ);
    cudaGetSymbolAddress((void**)&L0h, g_L0h);
    cudaGetSymbolAddress((void**)&L0l, g_L0l);
    cudaGetSymbolAddress((void**)&L1h, g_L1h);
    cudaGetSymbolAddress((void**)&L1l, g_L1l);
    cudaGetSymbolAddress((void**)&Bh1, g_Bh1);
    cudaGetSymbolAddress((void**)&Bl1, g_Bl1);
    cudaGetSymbolAddress((void**)&Bh2, g_Bh2);
    cudaGetSymbolAddress((void**)&Bl2, g_Bl2);

    const int GEMM_SMEM = NSTAGE * STAGE_B;   // 73728
    cudaFuncSetAttribute(cheb_gemm_mma<0>,
                         cudaFuncAttributeMaxDynamicSharedMemorySize, GEMM_SMEM);
    cudaFuncSetAttribute(cheb_gemm_mma<1>,
                         cudaFuncAttributeMaxDynamicSharedMemorySize, GEMM_SMEM);

    // ---- prep: split L matrices into bf16 hi/lo ----
    split_bf16<<<(M0 * M0 / 4 + 255) / 256, 256>>>(L0, L0h, L0l, M0 * M0 / 4);
    split_bf16<<<(M1 * M1 / 4 + 255) / 256, 256>>>(L1, L1h, L1l, M1 * M1 / 4);

    // ---- layer 1 Chebyshev recurrence ----
    transpose_x<<<dim3(M0 / 32, N_BATCH / 32), dim3(32, 8)>>>(x, T1p);
    // T0 transposed = x itself -> direct split, no transpose needed
    split_bf16<<<SL1 / 4 / 256, 256>>>(x, Bh1, Bl1, SL1 / 4);

    for (int k = 1; k < K_CHEB; k++) {
        cheb_gemm_mma<1><<<dim3(1, M0 / 128, Z1), 256, GEMM_SMEM>>>(
            L0h, L0l, Bh1, Bl1, nullptr, PZp, M0, NC1, KZ1, 0.f, 0);
        combine_split<<<dim3(M0 / 64, NC1 / 32), dim3(32, 8)>>>(
            (k >= 2) ? T1p + (size_t)(k - 2) * SL1 : nullptr,
            T1p + (size_t)k * SL1, Bh1, Bl1,
            (k == 1) ? 1.f : 2.f, (k >= 2) ? 1 : 0);
    }

    // ---- layer 1 contraction + relu + pool -> layer2 state 0 ----
    layer1_pool<<<M1, dim3(64, 4)>>>(W1, b1);

    // ---- layer 2 Chebyshev recurrence ----
    for (int k = 1; k < K_CHEB; k++) {
        split_trans<<<dim3(M1 / 64, NC2 / 32), dim3(32, 8)>>>(
            T2p + (size_t)(k - 1) * SL2, Bh2, Bl2, M1, NC2);
        cheb_gemm_mma<0><<<dim3(NC2 / 64, M1 / 128, 1), 256, GEMM_SMEM>>>(
            L1h, L1l, Bh2, Bl2,
            (k >= 2) ? T2p + (size_t)(k - 2) * SL2 : nullptr,
            T2p + (size_t)k * SL2, M1, NC2, M1,
            (k == 1) ? 1.f : 2.f, (k >= 2) ? 1 : 0);
    }

    // ---- layer 2 contraction + relu + pool ----
    cudaFuncSetAttribute(layer2_pool, cudaFuncAttributeMaxDynamicSharedMemorySize,
                         800 * 32 * 4);
    layer2_pool<<<dim3(128, 2), dim3(64, 2), 800 * 32 * 4>>>(W2, b2);

    // ---- FC head ----
    fc1_partial<<<dim3(16, 8), 256>>>(Wh);
    fc1_reduce<<<128, 256>>>(bh);
    fc2<<<5, 128>>>(Wo, bo, out);
}

// round 16
// speedup vs baseline: 1.9598x; 1.1116x over previous
#include <cuda_runtime.h>
#include <cuda_bf16.h>
#include <cstdint>
#include <cstddef>

// ---------------------------------------------------------------------------
// Problem constants
// ---------------------------------------------------------------------------
#define N_BATCH 64
#define M0 4096
#define M1 1024
#define K_CHEB 25
#define F0 32
#define F1 64
#define NC1 64
#define NC2 2048
#define SL1 (M0*NC1)
#define SL2 (M1*NC2)
#define Z1 8
#define KZ1 (M0/Z1)     // 512

// ---------------------------------------------------------------------------
// Device scratch
// ---------------------------------------------------------------------------
__device__ float g_T1[K_CHEB * SL1];
__device__ float g_T2[(size_t)K_CHEB * SL2];    // layer2 states S_k = T_k^T, [j][v]
__device__ float g_TMP[SL2];                    // layer1_pool output [u][j]
__device__ float g_PZ[(size_t)Z1 * SL1];
__device__ float g_OUT2[N_BATCH * 16384];
__device__ float g_P[8 * N_BATCH * 512];
__device__ float g_Yh[N_BATCH * 512];
__device__ __nv_bfloat16 g_L0h[(size_t)M0 * M0];
__device__ __nv_bfloat16 g_L0l[(size_t)M0 * M0];
__device__ __nv_bfloat16 g_L1h[(size_t)M1 * M1];
__device__ __nv_bfloat16 g_L1l[(size_t)M1 * M1];
__device__ __nv_bfloat16 g_Bh1[(size_t)NC1 * M0];
__device__ __nv_bfloat16 g_Bl1[(size_t)NC1 * M0];
__device__ __nv_bfloat16 g_Sh2[2][(size_t)SL2]; // ping-pong split of S_k
__device__ __nv_bfloat16 g_Sl2[2][(size_t)SL2];

// ---------------------------------------------------------------------------
// MMA / async-copy helpers (portable Ampere-era ops)
// ---------------------------------------------------------------------------
__device__ __forceinline__ uint32_t smem_u32(const void* p) {
    uint32_t a;
    asm("{ .reg .u64 t; cvta.to.shared.u64 t, %1; cvt.u32.u64 %0, t; }"
        : "=r"(a) : "l"(p));
    return a;
}
__device__ __forceinline__ void ldsm_x4(uint32_t* r, uint32_t addr) {
    asm volatile("ldmatrix.sync.aligned.m8n8.x4.shared.b16 {%0,%1,%2,%3}, [%4];"
        : "=r"(r[0]), "=r"(r[1]), "=r"(r[2]), "=r"(r[3]) : "r"(addr));
}
__device__ __forceinline__ void ldsm_x2(uint32_t* r, uint32_t addr) {
    asm volatile("ldmatrix.sync.aligned.m8n8.x2.shared.b16 {%0,%1}, [%2];"
        : "=r"(r[0]), "=r"(r[1]) : "r"(addr));
}
__device__ __forceinline__ void mma16816(float* c, const uint32_t* a,
                                         const uint32_t* b) {
    asm volatile(
        "mma.sync.aligned.m16n8k16.row.col.f32.bf16.bf16.f32 "
        "{%0,%1,%2,%3}, {%4,%5,%6,%7}, {%8,%9}, {%0,%1,%2,%3};"
        : "+f"(c[0]), "+f"(c[1]), "+f"(c[2]), "+f"(c[3])
        : "r"(a[0]), "r"(a[1]), "r"(a[2]), "r"(a[3]), "r"(b[0]), "r"(b[1]));
}
__device__ __forceinline__ void cp16(uint32_t saddr, const void* g) {
    asm volatile("cp.async.cg.shared.global [%0], [%1], 16;"
        :: "r"(saddr), "l"(g) : "memory");
}
#define CP_COMMIT() asm volatile("cp.async.commit_group;" ::: "memory")
#define CP_WAIT1()  asm volatile("cp.async.wait_group 1;" ::: "memory")

__device__ __forceinline__ void split2(float a, float b, uint32_t& h2, uint32_t& l2)
{
    __nv_bfloat16 ha = __float2bfloat16(a), hb = __float2bfloat16(b);
    float ra = __bfloat162float(ha), rb = __bfloat162float(hb);
    __nv_bfloat16 la = __float2bfloat16(a - ra), lb = __float2bfloat16(b - rb);
    h2 = (uint32_t)__bfloat16_as_ushort(ha) | ((uint32_t)__bfloat16_as_ushort(hb) << 16);
    l2 = (uint32_t)__bfloat16_as_ushort(la) | ((uint32_t)__bfloat16_as_ushort(lb) << 16);
}

// ---------------------------------------------------------------------------
// split_bf16: elementwise fp32 -> bf16 hi/lo (same layout)
// ---------------------------------------------------------------------------
__global__ void split_bf16(const float* __restrict__ src,
                           __nv_bfloat16* __restrict__ hi,
                           __nv_bfloat16* __restrict__ lo, int n4)
{
    int i = blockIdx.x * blockDim.x + threadIdx.x;
    if (i >= n4) return;
    float4 v = ((const float4*)src)[i];
    uint32_t h0, l0, h1, l1;
    split2(v.x, v.y, h0, l0);
    split2(v.z, v.w, h1, l1);
    ((uint2*)hi)[i] = make_uint2(h0, h1);
    ((uint2*)lo)[i] = make_uint2(l0, l1);
}

// ---------------------------------------------------------------------------
// trans_f32: in[R][C] -> out[C][R]  (layer1 -> layer2 bridge)
// ---------------------------------------------------------------------------
__global__ __launch_bounds__(256)
void trans_f32(const float* __restrict__ in, float* __restrict__ out,
               int R, int C)
{
    __shared__ float s[32][33];
    int r0 = blockIdx.y * 32, c0 = blockIdx.x * 32;
    int tx = threadIdx.x, ty = threadIdx.y;
    for (int r = ty; r < 32; r += 8)
        s[r][tx] = in[(size_t)(r0 + r) * C + c0 + tx];
    __syncthreads();
    for (int r = ty; r < 32; r += 8)
        out[(size_t)(c0 + r) * R + r0 + tx] = s[tx][r];
}

// ---------------------------------------------------------------------------
// combine_split (layer1): C = s2*sum_z PZ - hasA*A  (fp32 [u][n]),
// plus transposed bf16 hi/lo [n][u] for the next GEMM's B.
// ---------------------------------------------------------------------------
__global__ __launch_bounds__(256)
void combine_split(const float* __restrict__ Ap, float* __restrict__ Cp,
                   __nv_bfloat16* __restrict__ Hi, __nv_bfloat16* __restrict__ Lo,
                   float s2, int hasA)
{
    __shared__ float s[64][33];
    int m0 = blockIdx.x * 64, nc0 = blockIdx.y * 32;
    int tx = threadIdx.x, ty = threadIdx.y;
    for (int r = ty; r < 64; r += 8) {
        size_t off = (size_t)(m0 + r) * NC1 + nc0 + tx;
        float acc = 0.f;
#pragma unroll
        for (int z = 0; z < Z1; z++)
            acc += g_PZ[(size_t)z * SL1 + off];
        float c = s2 * acc;
        if (hasA) c -= Ap[off];
        Cp[off] = c;
        s[r][tx] = c;
    }
    __syncthreads();
    for (int r = ty; r < 32; r += 8) {
        int j = nc0 + r;
        uint32_t h2, l2;
        split2(s[tx * 2][r], s[tx * 2 + 1][r], h2, l2);
        ((uint32_t*)(Hi + (size_t)j * M0 + m0))[tx] = h2;
        ((uint32_t*)(Lo + (size_t)j * M0 + m0))[tx] = l2;
    }
}

// ---------------------------------------------------------------------------
// Transpose x (N,4096) -> T1 slab 0 as [u][n]
// ---------------------------------------------------------------------------
__global__ void transpose_x(const float* __restrict__ x, float* __restrict__ T0)
{
    __shared__ float s[32][33];
    int u0 = blockIdx.x * 32, n0 = blockIdx.y * 32;
    int tx = threadIdx.x, ty = threadIdx.y;
    for (int r = ty; r < 32; r += 8)
        s[r][tx] = x[(size_t)(n0 + r) * M0 + u0 + tx];
    __syncthreads();
    for (int r = ty; r < 32; r += 8)
        T0[(size_t)(u0 + r) * NC1 + n0 + tx] = s[tx][r];
}

// ---------------------------------------------------------------------------
// Tensor-core (mma.sync) Chebyshev GEMM, 128x64 CTA tile, 256 threads,
// cp.async 3-stage pipeline, SW64-swizzled smem (3 CTAs/SM).
//   D = A[128, KLEN] @ Brows[64, KLEN]^T
//   PARTIAL=1: raw D -> Cp slab blockIdx.z.
//   PARTIAL=0: C = s2*D - hasA*A; if doSplit also emit bf16 hi/lo of C
//              (same layout -> coalesced).
// ---------------------------------------------------------------------------
#define OFF_AH 0
#define OFF_AL 8192
#define OFF_BH 16384
#define OFF_BL 20480
#define STAGE_B 24576
#define NSTAGE 3

template<int PARTIAL>
__global__ __launch_bounds__(256, 3)
void cheb_gemm_mma(const __nv_bfloat16* __restrict__ Lh,
                   const __nv_bfloat16* __restrict__ Ll,
                   const __nv_bfloat16* __restrict__ Bh,
                   const __nv_bfloat16* __restrict__ Bl,
                   const float* __restrict__ Ap,
                   float* __restrict__ Cp,
                   __nv_bfloat16* __restrict__ Ho,
                   __nv_bfloat16* __restrict__ Lo,
                   int M, int NC, int KLEN, float s2, int hasA, int doSplit)
{
    extern __shared__ __align__(16) char dsm[];
    const uint32_t sb = smem_u32(dsm);

    const int tid  = threadIdx.x;
    const int lane = tid & 31;
    const int wid  = tid >> 5;
    const int wm   = wid & 1;
    const int wn   = wid >> 1;
    const int u0   = blockIdx.y * 128;
    const int j0   = blockIdx.x * 64;
    const int kz   = blockIdx.z * KLEN;
    const int KT   = KLEN >> 5;

    const int ar0  = tid >> 2;
    const int ch   = tid & 3;
    const int sw0  = (tid >> 3) & 3;
    const int acol = ch * 8;

    const __nv_bfloat16* gAh0 = Lh + (size_t)(u0 + ar0) * M + kz + acol;
    const __nv_bfloat16* gAh1 = Lh + (size_t)(u0 + ar0 + 64) * M + kz + acol;
    const __nv_bfloat16* gAl0 = Ll + (size_t)(u0 + ar0) * M + kz + acol;
    const __nv_bfloat16* gAl1 = Ll + (size_t)(u0 + ar0 + 64) * M + kz + acol;
    const __nv_bfloat16* gBh0 = Bh + (size_t)(j0 + ar0) * M + kz + acol;
    const __nv_bfloat16* gBl0 = Bl + (size_t)(j0 + ar0) * M + kz + acol;

    const uint32_t dA0 = (uint32_t)(ar0 * 64 + ((ch ^ sw0) * 16));
    const uint32_t dA1 = dA0 + 64 * 64;

    const int swA = ((lane & 15) >> 1) & 3;
    const uint32_t arowb = (uint32_t)((wm * 64 + (lane & 15)) * 64);
    const uint32_t csA0 = (uint32_t)((((lane >> 4)) ^ swA) * 16);
    const uint32_t csA1 = (uint32_t)(((((lane >> 4)) + 2) ^ swA) * 16);
    const int swB = ((lane & 7) >> 1) & 3;
    const uint32_t browb = (uint32_t)((wn * 16 + (lane & 7)) * 64);
    const uint32_t csB0 = (uint32_t)(((((lane >> 3) & 1)) ^ swB) * 16);
    const uint32_t csB1 = (uint32_t)((((((lane >> 3) & 1)) + 2) ^ swB) * 16);

    float acc[4][2][4];
#pragma unroll
    for (int ma = 0; ma < 4; ma++)
#pragma unroll
        for (int na = 0; na < 2; na++)
#pragma unroll
            for (int q = 0; q < 4; q++) acc[ma][na][q] = 0.f;

#define ISSUE(ktv)                                                            \
    do {                                                                      \
        uint32_t s_ = sb + ((ktv) % NSTAGE) * STAGE_B;                        \
        int o_ = (ktv) * 32;                                                  \
        cp16(s_ + OFF_AH + dA0, gAh0 + o_);                                   \
        cp16(s_ + OFF_AH + dA1, gAh1 + o_);                                   \
        cp16(s_ + OFF_AL + dA0, gAl0 + o_);                                   \
        cp16(s_ + OFF_AL + dA1, gAl1 + o_);                                   \
        cp16(s_ + OFF_BH + dA0, gBh0 + o_);                                   \
        cp16(s_ + OFF_BL + dA0, gBl0 + o_);                                   \
    } while (0)

    ISSUE(0); CP_COMMIT();
    if (KT > 1) ISSUE(1);
    CP_COMMIT();

    for (int kt = 0; kt < KT; kt++) {
        CP_WAIT1();
        __syncthreads();
        const uint32_t bufb = sb + (kt % NSTAGE) * STAGE_B;
        const uint32_t aAh = bufb + OFF_AH, aAl = bufb + OFF_AL;
        const uint32_t aBh = bufb + OFF_BH, aBl = bufb + OFF_BL;

#pragma unroll
        for (int ss = 0; ss < 2; ss++) {
            const uint32_t csA = ss ? csA1 : csA0;
            const uint32_t csB = ss ? csB1 : csB0;
            uint32_t bhf[2][2], blf[2][2];
#pragma unroll
            for (int na = 0; na < 2; na++) {
                uint32_t boff = browb + na * 512 + csB;
                ldsm_x2(bhf[na], aBh + boff);
                ldsm_x2(blf[na], aBl + boff);
            }
#pragma unroll
            for (int ma = 0; ma < 4; ma++) {
                uint32_t ah[4], al[4];
                uint32_t aoff = arowb + ma * 1024 + csA;
                ldsm_x4(ah, aAh + aoff);
                ldsm_x4(al, aAl + aoff);
#pragma unroll
                for (int na = 0; na < 2; na++) {
                    mma16816(acc[ma][na], ah, bhf[na]);
                    mma16816(acc[ma][na], ah, blf[na]);
                    mma16816(acc[ma][na], al, bhf[na]);
                }
            }
        }

        if (kt + NSTAGE - 1 < KT) ISSUE(kt + NSTAGE - 1);
        CP_COMMIT();
    }
#undef ISSUE

    // ---- epilogue ----
    size_t cbase = PARTIAL ? (size_t)blockIdx.z * M * NC : 0;
#pragma unroll
    for (int ma = 0; ma < 4; ma++) {
#pragma unroll
        for (int na = 0; na < 2; na++) {
            int r0 = u0 + wm * 64 + ma * 16 + (lane >> 2);
            int c  = j0 + wn * 16 + na * 8 + (lane & 3) * 2;
            size_t o0 = (size_t)r0 * NC + c;
            size_t o1 = (size_t)(r0 + 8) * NC + c;
            float2 v0 = make_float2(acc[ma][na][0], acc[ma][na][1]);
            float2 v1 = make_float2(acc[ma][na][2], acc[ma][na][3]);
            if (PARTIAL) {
                *(float2*)(Cp + cbase + o0) = v0;
                *(float2*)(Cp + cbase + o1) = v1;
            } else {
                v0.x *= s2; v0.y *= s2; v1.x *= s2; v1.y *= s2;
                if (hasA) {
                    float2 a0 = *(const float2*)(Ap + o0);
                    float2 a1 = *(const float2*)(Ap + o1);
                    v0.x -= a0.x; v0.y -= a0.y;
                    v1.x -= a1.x; v1.y -= a1.y;
                }
                *(float2*)(Cp + o0) = v0;
                *(float2*)(Cp + o1) = v1;
                if (doSplit) {
                    uint32_t h2, l2;
                    split2(v0.x, v0.y, h2, l2);
                    *(uint32_t*)(Ho + o0) = h2;
                    *(uint32_t*)(Lo + o0) = l2;
                    split2(v1.x, v1.y, h2, l2);
                    *(uint32_t*)(Ho + o1) = h2;
                    *(uint32_t*)(Lo + o1) = l2;
                }
            }
        }
    }
}

// ---------------------------------------------------------------------------
// Layer1 tail: relu(maxpool4(T1 @ W1) + b1) -> g_TMP [u1 (1024)][j (2048)]
// grid M1/4 = 256 blocks x (64, 4): u1 = blockIdx.x*4 + ty  in [0, 1024)
// ---------------------------------------------------------------------------
__global__ __launch_bounds__(256)
void layer1_pool(const float* __restrict__ W1, const float* __restrict__ b1)
{
    __shared__ float W1s[K_CHEB * F0];
    __shared__ float b1s[F0];
    int n   = threadIdx.x;
    int u1  = blockIdx.x * 4 + threadIdx.y;
    int tid = threadIdx.y * 64 + n;

    for (int i = tid; i < K_CHEB * F0; i += 256) W1s[i] = W1[i];
    if (tid < F0) b1s[tid] = b1[tid];
    __syncthreads();

    float m[F0];
#pragma unroll
    for (int f = 0; f < F0; f++) m[f] = -1e30f;

    for (int p = 0; p < 4; p++) {
        float acc[F0];
#pragma unroll
        for (int f = 0; f < F0; f++) acc[f] = 0.f;
        int u = u1 * 4 + p;
        const float* tp = g_T1 + (size_t)u * NC1 + n;
        for (int k = 0; k < K_CHEB; k++) {
            float t = tp[(size_t)k * SL1];
#pragma unroll
            for (int f = 0; f < F0; f++) acc[f] += t * W1s[k * F0 + f];
        }
#pragma unroll
        for (int f = 0; f < F0; f++) m[f] = fmaxf(m[f], acc[f]);
    }
    float* op = g_TMP + (size_t)u1 * NC2 + n * F0;
#pragma unroll
    for (int f = 0; f < F0; f++) op[f] = fmaxf(m[f] + b1s[f], 0.f);
}

// ---------------------------------------------------------------------------
// Layer2 tail (transposed state): OUT2 = relu(maxpool4 + b2)
// S layout: g_T2[k][j][v], j = n*32+f, v = node u.
// ---------------------------------------------------------------------------
__global__ __launch_bounds__(256)
void layer2_pool_s(const float* __restrict__ W2, const float* __restrict__ b2)
{
    __shared__ __align__(16) float sS[32][260];
    __shared__ float sW[32][64];
    const int tid = threadIdx.x;
    const int n   = blockIdx.x;
    const int ut  = blockIdx.y * 256;
    const int uq  = tid >> 2;
    const int fg  = tid & 3;

    float acc[4][16];
#pragma unroll
    for (int p = 0; p < 4; p++)
#pragma unroll
        for (int q = 0; q < 16; q++) acc[p][q] = 0.f;

    for (int k = 0; k < K_CHEB; k++) {
        const float* base = g_T2 + (size_t)k * SL2 + (size_t)(n * 32) * M1 + ut;
#pragma unroll
        for (int it = 0; it < 8; it++) {
            int row = it * 4 + (tid >> 6);
            int c4  = tid & 63;
            *(float4*)&sS[row][c4 * 4] = *(const float4*)(base + (size_t)row * M1 + c4 * 4);
        }
        for (int i = tid; i < 32 * 64; i += 256) {
            int f = i >> 6, fo = i & 63;
            sW[f][fo] = W2[(size_t)(f * K_CHEB + k) * F1 + fo];
        }
        __syncthreads();

#pragma unroll 4
        for (int f = 0; f < 32; f++) {
            float4 sv = *(const float4*)&sS[f][uq * 4];
            const float* w = &sW[f][fg * 16];
#pragma unroll
            for (int q = 0; q < 16; q++) {
                float wq = w[q];
                acc[0][q] += sv.x * wq;
                acc[1][q] += sv.y * wq;
                acc[2][q] += sv.z * wq;
                acc[3][q] += sv.w * wq;
            }
        }
        __syncthreads();
    }

    int u1 = blockIdx.y * 64 + uq;
    float* op = g_OUT2 + (size_t)n * 16384 + u1 * F1 + fg * 16;
#pragma unroll
    for (int q = 0; q < 16; q++) {
        float m = fmaxf(fmaxf(acc[0][q], acc[1][q]), fmaxf(acc[2][q], acc[3][q]));
        op[q] = fmaxf(m + b2[fg * 16 + q], 0.f);
    }
}

// ---------------------------------------------------------------------------
// FC head
// ---------------------------------------------------------------------------
__global__ __launch_bounds__(256)
void fc1_partial(const float* __restrict__ Wh)
{
    __shared__ float As[32][68];
    __shared__ float Ws[32][32];
    int tid  = threadIdx.x;
    int j0   = blockIdx.x * 32;
    int kz   = blockIdx.y * 2048;
    int tcol = tid & 31;
    int n0   = (tid >> 5) * 8;
    float acc[8];
#pragma unroll
    for (int i = 0; i < 8; i++) acc[i] = 0.f;

    for (int k0 = 0; k0 < 2048; k0 += 32) {
        __syncthreads();
#pragma unroll
        for (int it = 0; it < 2; it++) {
            int idx = tid * 4 + it * 1024;
            int nn = idx >> 5;
            int kk = idx & 31;
            float4 v = *(const float4*)(g_OUT2 + (size_t)nn * 16384 + kz + k0 + kk);
            As[kk + 0][nn] = v.x; As[kk + 1][nn] = v.y;
            As[kk + 2][nn] = v.z; As[kk + 3][nn] = v.w;
        }
#pragma unroll
        for (int i = tid; i < 1024; i += 256) {
            int r = i >> 5, c = i & 31;
            Ws[r][c] = Wh[(size_t)(kz + k0 + r) * 512 + j0 + c];
        }
        __syncthreads();
#pragma unroll
        for (int kk = 0; kk < 32; kk++) {
            float w = Ws[kk][tcol];
            float4 a0 = *(const float4*)&As[kk][n0];
            float4 a1 = *(const float4*)&As[kk][n0 + 4];
            acc[0] += a0.x * w; acc[1] += a0.y * w;
            acc[2] += a0.z * w; acc[3] += a0.w * w;
            acc[4] += a1.x * w; acc[5] += a1.y * w;
            acc[6] += a1.z * w; acc[7] += a1.w * w;
        }
    }
#pragma unroll
    for (int i = 0; i < 8; i++)
        g_P[(size_t)blockIdx.y * 32768 + (size_t)(n0 + i) * 512 + j0 + tcol] = acc[i];
}

__global__ void fc1_reduce(const float* __restrict__ bh)
{
    int i = blockIdx.x * blockDim.x + threadIdx.x;
    float s = 0.f;
#pragma unroll
    for (int z = 0; z < 8; z++) s += g_P[(size_t)z * 32768 + i];
    g_Yh[i] = fmaxf(s + bh[i & 511], 0.f);
}

__global__ void fc2(const float* __restrict__ Wo, const float* __restrict__ bo,
                    float* __restrict__ out)
{
    int g = blockIdx.x * blockDim.x + threadIdx.x;
    if (g >= 640) return;
    int n = g / 10, o = g % 10;
    float s = bo[o];
    const float* y = g_Yh + (size_t)n * 512;
    for (int j = 0; j < 512; j++) s += y[j] * Wo[j * 10 + o];
    out[g] = s;
}

// ---------------------------------------------------------------------------
// Host driver
// ---------------------------------------------------------------------------
extern "C" void kernel_launch(void* const* d_in, const int* in_sizes, int n_in,
                              void* d_out, int out_size)
{
    const float* x  = (const float*)d_in[0];
    const float* L0 = (const float*)d_in[1];
    const float* L1 = (const float*)d_in[2];
    const float* W1 = (const float*)d_in[3];
    const float* b1 = (const float*)d_in[4];
    const float* W2 = (const float*)d_in[5];
    const float* b2 = (const float*)d_in[6];
    const float* Wh = (const float*)d_in[7];
    const float* bh = (const float*)d_in[8];
    const float* Wo = (const float*)d_in[9];
    const float* bo = (const float*)d_in[10];
    float* out = (float*)d_out;

    float *T1p, *T2p, *PZp, *TMPp;
    __nv_bfloat16 *L0h, *L0l, *L1h, *L1l, *Bh1, *Bl1, *Sh2, *Sl2;
    cudaGetSymbolAddress((void**)&T1p, g_T1);
    cudaGetSymbolAddress((void**)&T2p, g_T2);
    cudaGetSymbolAddress((void**)&PZp, g_PZ);
    cudaGetSymbolAddress((void**)&TMPp, g_TMP);
    cudaGetSymbolAddress((void**)&L0h, g_L0h);
    cudaGetSymbolAddress((void**)&L0l, g_L0l);
    cudaGetSymbolAddress((void**)&L1h, g_L1h);
    cudaGetSymbolAddress((void**)&L1l, g_L1l);
    cudaGetSymbolAddress((void**)&Bh1, g_Bh1);
    cudaGetSymbolAddress((void**)&Bl1, g_Bl1);
    cudaGetSymbolAddress((void**)&Sh2, g_Sh2);
    cudaGetSymbolAddress((void**)&Sl2, g_Sl2);

    const int GEMM_SMEM = NSTAGE * STAGE_B;   // 73728
    cudaFuncSetAttribute(cheb_gemm_mma<0>,
                         cudaFuncAttributeMaxDynamicSharedMemorySize, GEMM_SMEM);
    cudaFuncSetAttribute(cheb_gemm_mma<1>,
                         cudaFuncAttributeMaxDynamicSharedMemorySize, GEMM_SMEM);

    // ---- prep: split L matrices into bf16 hi/lo ----
    split_bf16<<<(M0 * M0 / 4 + 255) / 256, 256>>>(L0, L0h, L0l, M0 * M0 / 4);
    split_bf16<<<(M1 * M1 / 4 + 255) / 256, 256>>>(L1, L1h, L1l, M1 * M1 / 4);

    // ---- layer 1 Chebyshev recurrence ----
    transpose_x<<<dim3(M0 / 32, N_BATCH / 32), dim3(32, 8)>>>(x, T1p);
    split_bf16<<<SL1 / 4 / 256, 256>>>(x, Bh1, Bl1, SL1 / 4);

    for (int k = 1; k < K_CHEB; k++) {
        cheb_gemm_mma<1><<<dim3(1, M0 / 128, Z1), 256, GEMM_SMEM>>>(
            L0h, L0l, Bh1, Bl1, nullptr, PZp, nullptr, nullptr,
            M0, NC1, KZ1, 0.f, 0, 0);
        combine_split<<<dim3(M0 / 64, NC1 / 32), dim3(32, 8)>>>(
            (k >= 2) ? T1p + (size_t)(k - 2) * SL1 : nullptr,
            T1p + (size_t)k * SL1, Bh1, Bl1,
            (k == 1) ? 1.f : 2.f, (k >= 2) ? 1 : 0);
    }

    // ---- layer 1 tail -> bridge to transposed layer-2 state S0 ----
    layer1_pool<<<M1 / 4, dim3(64, 4)>>>(W1, b1);
    trans_f32<<<dim3(NC2 / 32, M1 / 32), dim3(32, 8)>>>(TMPp, T2p, M1, NC2);
    split_bf16<<<SL2 / 4 / 256, 256>>>(T2p, Sh2, Sl2, SL2 / 4);

    // ---- layer 2 Chebyshev recurrence, transposed: S_k = s2*S_{k-1}@L - S_{k-2}
    for (int k = 1; k < K_CHEB; k++) {
        int rb = (k - 1) & 1, wb = k & 1;
        cheb_gemm_mma<0><<<dim3(M1 / 64, NC2 / 128, 1), 256, GEMM_SMEM>>>(
            Sh2 + (size_t)rb * SL2, Sl2 + (size_t)rb * SL2, L1h, L1l,
            (k >= 2) ? T2p + (size_t)(k - 2) * SL2 : nullptr,
            T2p + (size_t)k * SL2,
            Sh2 + (size_t)wb * SL2, Sl2 + (size_t)wb * SL2,
            M1, M1, M1, (k == 1) ? 1.f : 2.f, (k >= 2) ? 1 : 0,
            (k < K_CHEB - 1) ? 1 : 0);
    }

    // ---- layer 2 contraction + relu + pool ----
    layer2_pool_s<<<dim3(N_BATCH, 4), 256>>>(W2, b2);

    // ---- FC head ----
    fc1_partial<<<dim3(16, 8), 256>>>(Wh);
    fc1_reduce<<<128, 256>>>(bh);
    fc2<<<5, 128>>>(Wo, bo, out);
}